// round 13
// baseline (speedup 1.0000x reference)
#include <cuda_runtime.h>
#include <cuda_fp16.h>
#include <cstdint>

#define N_NODES 8192
#define C_CH    128
#define N_EDGES 262144
#define KPACK   128            // single fp16 product: K = C

// ---------------- scratch (device globals; no allocation allowed) ----------------
__device__ __align__(16) float g_dis[N_NODES];
__device__ __align__(16) int   g_cnt[N_NODES];
__device__ __align__(16) int   g_off[N_NODES];
__device__ __align__(16) int   g_cur[N_NODES];
__device__ __align__(16) int2  g_csr[N_EDGES];
__device__ __align__(16) float g_h  [N_NODES * C_CH];   // NodeModel ping
__device__ __align__(16) float g_ha [N_NODES * C_CH];   // NodeModel pong
__device__ __align__(16) float g_s  [N_NODES * C_CH];   // pre-agg x@Ws
__device__ __align__(16) float g_t  [N_NODES * C_CH];   // pre-agg x@Wt
// packed fp16 decoder operands: A=Sh, B=Th
__device__ __align__(16) __half g_apack[N_NODES * KPACK];
__device__ __align__(16) __half g_bpack[N_NODES * KPACK];
__device__ int g_is64;

__device__ __forceinline__ float* buf_ptr(int s) {
    switch (s) {
        case 1: return g_s;
        case 2: return g_t;
        case 5: return g_ha;
        default: return g_h;
    }
}

// ---------------- preproc 1: edge dtype detect (block 0) + zero counts ----------------
__global__ void k_pre1(const int* __restrict__ v) {
    if (blockIdx.x == 0) {
        __shared__ int any;
        if (threadIdx.x == 0) any = 0;
        __syncthreads();
        int acc = 0;
        for (int i = threadIdx.x; i < 8192; i += 256) {
            int idx = i * 64 + 1;            // odd word, < 2*E
            acc |= v[idx];
        }
        if (acc) atomicOr(&any, 1);
        __syncthreads();
        if (threadIdx.x == 0) g_is64 = (any == 0) ? 1 : 0;
    } else {
        int i = (blockIdx.x - 1) * 256 + threadIdx.x;
        g_cnt[i] = 0;
    }
}

__device__ __forceinline__ int edge_at(const void* ei, int idx) {
    int v;
    if (g_is64) v = (int)((const long long*)ei)[idx];
    else        v = ((const int*)ei)[idx];
    return v & (N_NODES - 1);
}

__global__ void k_deg(const void* __restrict__ ei) {
    int e = blockIdx.x * blockDim.x + threadIdx.x;
    if (e < N_EDGES) atomicAdd(&g_cnt[edge_at(ei, N_EDGES + e)], 1);
}

// scan (1 block) + dis computation fused
__global__ void k_scan_dis() {
    __shared__ int part[1024];
    int t = threadIdx.x;
    int base = t * 8;
    int loc[8];
    int s = 0;
#pragma unroll
    for (int i = 0; i < 8; i++) {
        loc[i] = g_cnt[base + i];
        g_dis[base + i] = rsqrtf((float)loc[i] + 1.0f);
        s += loc[i];
    }
    part[t] = s;
    __syncthreads();
    for (int off = 1; off < 1024; off <<= 1) {
        int v = 0;
        if (t >= off) v = part[t - off];
        __syncthreads();
        part[t] += v;
        __syncthreads();
    }
    int run = part[t] - s;
#pragma unroll
    for (int i = 0; i < 8; i++) {
        g_off[base + i] = run;
        g_cur[base + i] = run;
        run += loc[i];
    }
}

__global__ void k_fill(const void* __restrict__ ei) {
    int e = blockIdx.x * blockDim.x + threadIdx.x;
    if (e < N_EDGES) {
        int s = edge_at(ei, e);
        int d = edge_at(ei, N_EDGES + e);
        float w = g_dis[s] * g_dis[d];
        int p = atomicAdd(&g_cur[d], 1);
        if (p < N_EDGES) g_csr[p] = make_int2(s, __float_as_int(w));
    }
}

// ---------------- shared agg routine: one warp aggregates one node ----------------
__device__ __forceinline__ float4 agg_node(const float4* __restrict__ H4,
                                           int node, int lane,
                                           float4 bb, int relu) {
    float  di = g_dis[node];
    float  dd = di * di;
    float4 h  = H4[(size_t)node * 32 + lane];
    float4 acc;
    acc.x = fmaf(h.x, dd, bb.x);
    acc.y = fmaf(h.y, dd, bb.y);
    acc.z = fmaf(h.z, dd, bb.z);
    acc.w = fmaf(h.w, dd, bb.w);
    float4 acc2 = make_float4(0.f, 0.f, 0.f, 0.f);

    int start = g_off[node];
    int cnt   = g_cnt[node];
    int j = 0;
    for (; j + 1 < cnt; j += 2) {
        int2 e0 = g_csr[start + j];
        int2 e1 = g_csr[start + j + 1];
        float w0 = __int_as_float(e0.y);
        float w1 = __int_as_float(e1.y);
        float4 v0 = H4[(size_t)e0.x * 32 + lane];
        float4 v1 = H4[(size_t)e1.x * 32 + lane];
        acc.x  = fmaf(v0.x, w0, acc.x);  acc.y  = fmaf(v0.y, w0, acc.y);
        acc.z  = fmaf(v0.z, w0, acc.z);  acc.w  = fmaf(v0.w, w0, acc.w);
        acc2.x = fmaf(v1.x, w1, acc2.x); acc2.y = fmaf(v1.y, w1, acc2.y);
        acc2.z = fmaf(v1.z, w1, acc2.z); acc2.w = fmaf(v1.w, w1, acc2.w);
    }
    if (j < cnt) {
        int2 e0 = g_csr[start + j];
        float w0 = __int_as_float(e0.y);
        float4 v0 = H4[(size_t)e0.x * 32 + lane];
        acc.x = fmaf(v0.x, w0, acc.x); acc.y = fmaf(v0.y, w0, acc.y);
        acc.z = fmaf(v0.z, w0, acc.z); acc.w = fmaf(v0.w, w0, acc.w);
    }
    acc.x += acc2.x; acc.y += acc2.y; acc.z += acc2.z; acc.w += acc2.w;
    if (relu) {
        acc.x = fmaxf(acc.x, 0.f); acc.y = fmaxf(acc.y, 0.f);
        acc.z = fmaxf(acc.z, 0.f); acc.w = fmaxf(acc.w, 0.f);
    }
    return acc;
}

// ---------------- fused layer: out = (relu?(agg(in)+b)) @ W  (row-local fusion) ----------------
// 1024 blocks x 256 threads: 8 warps gather 8 nodes (full occupancy preserved),
// then the same block computes those 8 output rows x W. W stays L1-resident.
__global__ __launch_bounds__(256) void k_layer(int inSel,
                                               const float* __restrict__ bias,
                                               int relu,
                                               const float* __restrict__ W,
                                               int outSel) {
    __shared__ float Asm[8 * 132];

    const float4* H4 = (const float4*)buf_ptr(inSel);
    float* Ob = buf_ptr(outSel);
    int tid = threadIdx.x, wid = tid >> 5, lane = tid & 31;
    int nb = blockIdx.x * 8;

    // phase 1: gather (identical inner loop to k_agg)
    float4 bb = ((const float4*)bias)[lane];
    float4 a = agg_node(H4, nb + wid, lane, bb, relu);
    *(float4*)&Asm[wid * 132 + lane * 4] = a;
    __syncthreads();

    // phase 2: row-local GEMM: out[r] = Asm[r] @ W, thread -> (row=wid, cols=lane*4..+3)
    float4 acc = make_float4(0.f, 0.f, 0.f, 0.f);
    const float* arow = &Asm[wid * 132];
#pragma unroll 8
    for (int k = 0; k < 128; k++) {
        float av = arow[k];                             // smem broadcast
        float4 w4 = *(const float4*)&W[(size_t)k * 128 + lane * 4];
        acc.x = fmaf(av, w4.x, acc.x);
        acc.y = fmaf(av, w4.y, acc.y);
        acc.z = fmaf(av, w4.z, acc.z);
        acc.w = fmaf(av, w4.w, acc.w);
    }
    *(float4*)&Ob[(size_t)(nb + wid) * 128 + lane * 4] = acc;
}

// ---------------- final agg -> hout (1024 blocks) ----------------
__global__ __launch_bounds__(256) void k_agg_final(const float* __restrict__ bias,
                                                   float* __restrict__ O, int inSel) {
    int warp = threadIdx.x >> 5, lane = threadIdx.x & 31;
    int node = blockIdx.x * 8 + warp;
    const float4* H4 = (const float4*)buf_ptr(inSel);
    float4 bb = ((const float4*)bias)[lane];
    float4 acc = agg_node(H4, node, lane, bb, 1);
    ((float4*)O)[(size_t)node * 32 + lane] = acc;
}

// ---------------- k_gemm_x3: x @ {Ws, Wt, W1} in one launch (gridDim.y=3) ----------------
__global__ __launch_bounds__(256) void k_gemm_x3(const float* __restrict__ x,
                                                 const float* __restrict__ Ws,
                                                 const float* __restrict__ Wt,
                                                 const float* __restrict__ W1) {
    __shared__ float Wsm[32 * 128];
    __shared__ float Asm[64 * 40];

    const float* W;
    float* Ob;
    if (blockIdx.y == 0)      { W = Ws; Ob = g_s; }
    else if (blockIdx.y == 1) { W = Wt; Ob = g_t; }
    else                      { W = W1; Ob = g_h; }

    int tid = threadIdx.x;
    int rb  = blockIdx.x * 64;
    int cg = tid & 15, rg = tid >> 4;
    int r0 = rg * 4, c0 = cg * 8;

    float acc[4][8];
#pragma unroll
    for (int i = 0; i < 4; i++)
#pragma unroll
        for (int j = 0; j < 8; j++) acc[i][j] = 0.f;

    for (int c = 0; c < 4; c++) {
        int kc0 = c * 32;
        __syncthreads();
#pragma unroll
        for (int i = 0; i < 4; i++) {
            int idx = tid + i * 256;
            int k = idx >> 5, c4 = idx & 31;
            *(float4*)&Wsm[k * 128 + c4 * 4] =
                *(const float4*)&W[(size_t)(kc0 + k) * 128 + c4 * 4];
        }
#pragma unroll
        for (int i = 0; i < 2; i++) {
            int idx = tid + i * 256;
            int row = idx >> 3, c4 = idx & 7;
            *(float4*)&Asm[row * 40 + c4 * 4] =
                *(const float4*)&x[(size_t)(rb + row) * 128 + kc0 + c4 * 4];
        }
        __syncthreads();

#pragma unroll
        for (int k = 0; k < 32; k += 4) {
            float4 a[4];
#pragma unroll
            for (int i = 0; i < 4; i++) a[i] = *(const float4*)&Asm[(r0 + i) * 40 + k];
#pragma unroll
            for (int kk = 0; kk < 4; kk++) {
                float4 bLo = *(const float4*)&Wsm[(k + kk) * 128 + c0];
                float4 bHi = *(const float4*)&Wsm[(k + kk) * 128 + c0 + 4];
                float bv[8] = {bLo.x, bLo.y, bLo.z, bLo.w, bHi.x, bHi.y, bHi.z, bHi.w};
#pragma unroll
                for (int i = 0; i < 4; i++) {
                    float av = (kk == 0) ? a[i].x : (kk == 1) ? a[i].y
                               : (kk == 2) ? a[i].z : a[i].w;
#pragma unroll
                    for (int j = 0; j < 8; j++)
                        acc[i][j] = fmaf(av, bv[j], acc[i][j]);
                }
            }
        }
    }

#pragma unroll
    for (int i = 0; i < 4; i++) {
        float4 lo = make_float4(acc[i][0], acc[i][1], acc[i][2], acc[i][3]);
        float4 hi = make_float4(acc[i][4], acc[i][5], acc[i][6], acc[i][7]);
        size_t base = (size_t)(rb + r0 + i) * 128 + c0;
        *(float4*)&Ob[base]     = lo;
        *(float4*)&Ob[base + 4] = hi;
    }
}

// ---------------- k_agg_st (2048 blocks): agg s and t + write fp16 packs ----------------
__global__ __launch_bounds__(256) void k_agg_st(const float* __restrict__ bs,
                                                const float* __restrict__ bt) {
    int warp = threadIdx.x >> 5, lane = threadIdx.x & 31;
    int smode = (blockIdx.x < 1024);
    int node = (smode ? blockIdx.x : blockIdx.x - 1024) * 8 + warp;
    const float4* H4 = (const float4*)(smode ? g_s : g_t);
    const float*  bias = smode ? bs : bt;

    float4 bb = ((const float4*)bias)[lane];
    float4 acc = agg_node(H4, node, lane, bb, 0);

    __half p0 = __float2half_rn(acc.x), p1 = __float2half_rn(acc.y);
    __half p2 = __float2half_rn(acc.z), p3 = __float2half_rn(acc.w);
    __half pk[4] = {p0, p1, p2, p3};
    size_t pb = (size_t)node * KPACK + lane * 4;
    if (smode) *(uint2*)&g_apack[pb] = *(uint2*)pk;
    else       *(uint2*)&g_bpack[pb] = *(uint2*)pk;
}

// ---------------- HMMA decoder: adj = Apack @ Bpack^T (fp16, K=128) ----------------
__device__ __forceinline__ void ldsm_x4(uint32_t& r0, uint32_t& r1,
                                        uint32_t& r2, uint32_t& r3, uint32_t a) {
    asm volatile("ldmatrix.sync.aligned.m8n8.x4.shared.b16 {%0,%1,%2,%3}, [%4];"
                 : "=r"(r0), "=r"(r1), "=r"(r2), "=r"(r3) : "r"(a));
}
__device__ __forceinline__ void mma_f16(float& c0, float& c1, float& c2, float& c3,
                                        uint32_t a0, uint32_t a1, uint32_t a2, uint32_t a3,
                                        uint32_t b0, uint32_t b1) {
    asm volatile(
        "mma.sync.aligned.m16n8k16.row.col.f32.f16.f16.f32 "
        "{%0,%1,%2,%3}, {%4,%5,%6,%7}, {%8,%9}, {%0,%1,%2,%3};"
        : "+f"(c0), "+f"(c1), "+f"(c2), "+f"(c3)
        : "r"(a0), "r"(a1), "r"(a2), "r"(a3), "r"(b0), "r"(b1));
}
__device__ __forceinline__ void cp_async16(uint32_t dst, const void* src) {
    asm volatile("cp.async.cg.shared.global [%0], [%1], 16;" :: "r"(dst), "l"(src));
}
#define CP_COMMIT() asm volatile("cp.async.commit_group;" ::: "memory")
#define CP_WAIT(n)  asm volatile("cp.async.wait_group %0;" :: "n"(n) : "memory")
#define SWZ(off) ((off) ^ (((off) >> 3) & 0x70))

#define A_BYTES   32768        // 256 rows x 128B (Kc=64 halves)
#define B_BYTES   16384        // 128 rows x 128B
#define BUF_BYTES (A_BYTES + B_BYTES)
#define DEC_SMEM  (2 * BUF_BYTES)   // 96 KB

__global__ __launch_bounds__(256) void k_decoder(float* __restrict__ adj) {
    extern __shared__ __align__(16) char smem[];
    uint32_t sbase = (uint32_t)__cvta_generic_to_shared(smem);

    int tid  = threadIdx.x;
    int wid  = tid >> 5, lane = tid & 31;
    int wm   = wid >> 1, wn = wid & 1;        // 4 x 2 warp grid, warp tile m64 n64
    int cb   = blockIdx.x * 128;              // N offset
    int rb   = blockIdx.y * 256;              // M offset

    float acc[4][8][4];
#pragma unroll
    for (int m = 0; m < 4; m++)
#pragma unroll
        for (int n = 0; n < 8; n++)
#pragma unroll
            for (int r = 0; r < 4; r++) acc[m][n][r] = 0.f;

#define LOAD_CHUNK(c, buf) do {                                                  \
    int kc0 = (c) * 64;                                                          \
    uint32_t base = sbase + (buf) * BUF_BYTES;                                   \
    _Pragma("unroll")                                                            \
    for (int i = 0; i < 12; i++) {                                               \
        int seg = tid + i * 256;                                                 \
        if (seg < 2048) {                                                        \
            int row = seg >> 3, sgi = seg & 7;                                   \
            uint32_t off = (uint32_t)(row * 128 + sgi * 16);                     \
            cp_async16(base + SWZ(off),                                          \
                       &g_apack[(size_t)(rb + row) * KPACK + kc0 + sgi * 8]);    \
        } else {                                                                 \
            int bseg = seg - 2048;                                               \
            int row = bseg >> 3, sgi = bseg & 7;                                 \
            uint32_t off = (uint32_t)(row * 128 + sgi * 16);                     \
            cp_async16(base + A_BYTES + SWZ(off),                                \
                       &g_bpack[(size_t)(cb + row) * KPACK + kc0 + sgi * 8]);    \
        }                                                                        \
    }                                                                            \
} while (0)

    LOAD_CHUNK(0, 0);
    CP_COMMIT();

#pragma unroll 1
    for (int c = 0; c < 2; c++) {
        int buf = c & 1;
        if (c < 1) {
            LOAD_CHUNK(c + 1, buf ^ 1);
            CP_COMMIT();
            CP_WAIT(1);
        } else {
            CP_WAIT(0);
        }
        __syncthreads();

        uint32_t abase = sbase + buf * BUF_BYTES;
        uint32_t bbase = abase + A_BYTES;
#pragma unroll
        for (int ks = 0; ks < 4; ks++) {
            uint32_t a[4][4], b[4][4];
#pragma unroll
            for (int mt = 0; mt < 4; mt++) {
                int row = wm * 64 + mt * 16 + (lane & 15);
                uint32_t off = (uint32_t)(row * 128 + ks * 32 + ((lane >> 4) & 1) * 16);
                ldsm_x4(a[mt][0], a[mt][1], a[mt][2], a[mt][3], abase + SWZ(off));
            }
#pragma unroll
            for (int nt = 0; nt < 4; nt++) {
                int row = wn * 64 + nt * 16 + (lane & 15);
                uint32_t off = (uint32_t)(row * 128 + ks * 32 + ((lane >> 4) & 1) * 16);
                ldsm_x4(b[nt][0], b[nt][1], b[nt][2], b[nt][3], bbase + SWZ(off));
            }
#pragma unroll
            for (int mt = 0; mt < 4; mt++)
#pragma unroll
                for (int nt = 0; nt < 4; nt++) {
                    mma_f16(acc[mt][nt * 2][0], acc[mt][nt * 2][1],
                            acc[mt][nt * 2][2], acc[mt][nt * 2][3],
                            a[mt][0], a[mt][1], a[mt][2], a[mt][3],
                            b[nt][0], b[nt][2]);
                    mma_f16(acc[mt][nt * 2 + 1][0], acc[mt][nt * 2 + 1][1],
                            acc[mt][nt * 2 + 1][2], acc[mt][nt * 2 + 1][3],
                            a[mt][0], a[mt][1], a[mt][2], a[mt][3],
                            b[nt][1], b[nt][3]);
                }
        }
        __syncthreads();
    }

#pragma unroll
    for (int mt = 0; mt < 4; mt++) {
#pragma unroll
        for (int nt = 0; nt < 8; nt++) {
            int row = rb + wm * 64 + mt * 16 + (lane >> 2);
            int col = cb + wn * 64 + nt * 8 + (lane & 3) * 2;
            *(float2*)&adj[(size_t)row * 8192 + col] =
                make_float2(acc[mt][nt][0], acc[mt][nt][1]);
            *(float2*)&adj[(size_t)(row + 8) * 8192 + col] =
                make_float2(acc[mt][nt][2], acc[mt][nt][3]);
        }
    }
}

// ---------------- launch: two-arm schedule, fused NodeModel layers ----------------
extern "C" void kernel_launch(void* const* d_in, const int* in_sizes, int n_in,
                              void* d_out, int out_size) {
    (void)in_sizes; (void)n_in;
    const float* x  = (const float*)d_in[0];
    const void*  ei = d_in[1];
    const float *Ws = (const float*)d_in[2],  *bs  = (const float*)d_in[3];
    const float *Wt = (const float*)d_in[4],  *bt  = (const float*)d_in[5];
    const float *W1 = (const float*)d_in[6],  *b1  = (const float*)d_in[7];
    const float *W2 = (const float*)d_in[8],  *b2  = (const float*)d_in[9];
    const float *Wmu= (const float*)d_in[10], *bmu = (const float*)d_in[11];
    const float *W5 = (const float*)d_in[12], *b5  = (const float*)d_in[13];
    const float *W6 = (const float*)d_in[14], *b6  = (const float*)d_in[15];

    float* adj  = (float*)d_out;
    float* hout = (float*)d_out + ((size_t)out_size - (size_t)N_NODES * C_CH);

    cudaFuncSetAttribute(k_decoder, cudaFuncAttributeMaxDynamicSharedMemorySize,
                         DEC_SMEM);

    cudaStream_t sB;
    cudaStreamCreateWithFlags(&sB, cudaStreamNonBlocking);
    cudaEvent_t evStart, evPre, evX, evB;
    cudaEventCreateWithFlags(&evStart, cudaEventDisableTiming);
    cudaEventCreateWithFlags(&evPre,   cudaEventDisableTiming);
    cudaEventCreateWithFlags(&evX,     cudaEventDisableTiming);
    cudaEventCreateWithFlags(&evB,     cudaEventDisableTiming);

    // ---- fork ----
    cudaEventRecord(evStart, 0);
    cudaStreamWaitEvent(sB, evStart, 0);

    // ---- side stream: preprocessing (needs only ei) ----
    k_pre1<<<33, 256, 0, sB>>>((const int*)ei);
    k_deg<<<N_EDGES / 256, 256, 0, sB>>>(ei);
    k_scan_dis<<<1, 1024, 0, sB>>>();
    k_fill<<<N_EDGES / 256, 256, 0, sB>>>(ei);
    cudaEventRecord(evPre, sB);

    // ---- main stream: x @ {Ws, Wt, W1} (needs only x), overlapped with preproc ----
    k_gemm_x3<<<dim3(128, 3), 256>>>(x, Ws, Wt, W1);
    cudaEventRecord(evX, 0);

    // ---- side stream: fused NodeModel chain ----
    // chain: g_h = x@W1 -> [agg+relu]@W2 -> [agg+relu]@Wmu -> [agg]@W5 -> [agg+relu]@W6 -> agg+relu
    cudaStreamWaitEvent(sB, evX, 0);
    k_layer<<<1024, 256, 0, sB>>>(0, b1,  1, W2,  5);   // g_h  -> g_ha
    k_layer<<<1024, 256, 0, sB>>>(5, b2,  1, Wmu, 0);   // g_ha -> g_h
    k_layer<<<1024, 256, 0, sB>>>(0, bmu, 0, W5,  5);   // g_h  -> g_ha
    k_layer<<<1024, 256, 0, sB>>>(5, b5,  1, W6,  0);   // g_ha -> g_h
    k_agg_final<<<1024, 256, 0, sB>>>(b6, hout, 0);
    cudaEventRecord(evB, sB);

    // ---- main stream: s/t agg + packs (needs preproc + gemm_x3), then decoder ----
    cudaStreamWaitEvent(0, evPre, 0);
    k_agg_st<<<2048, 256>>>(bs, bt);
    k_decoder<<<dim3(64, 32), 256, DEC_SMEM>>>(adj);

    // ---- join ----
    cudaStreamWaitEvent(0, evB, 0);
}

// round 14
// speedup vs baseline: 1.0678x; 1.0678x over previous
#include <cuda_runtime.h>
#include <cuda_fp16.h>
#include <cstdint>

#define N_NODES 8192
#define C_CH    128
#define N_EDGES 262144
#define KPACK   128            // single fp16 product: K = C

// ---------------- scratch (device globals; no allocation allowed) ----------------
__device__ __align__(16) float g_dis[N_NODES];
__device__ __align__(16) int   g_cnt[N_NODES];
__device__ __align__(16) int   g_off[N_NODES];
__device__ __align__(16) int   g_cur[N_NODES];
__device__ __align__(16) int2  g_csr[N_EDGES];
__device__ __align__(16) float g_h  [N_NODES * C_CH];   // NodeModel gemm output (fp32)
__device__ __align__(16) float g_u1 [N_NODES * C_CH];
__device__ __align__(16) float g_u2 [N_NODES * C_CH];
// fp16 gather mirrors (halve agg L2 traffic)
__device__ __align__(16) __half g_h16[N_NODES * C_CH];
__device__ __align__(16) __half g_s16[N_NODES * C_CH];
__device__ __align__(16) __half g_t16[N_NODES * C_CH];
// packed fp16 decoder operands: A=Sh, B=Th
__device__ __align__(16) __half g_apack[N_NODES * KPACK];
__device__ __align__(16) __half g_bpack[N_NODES * KPACK];
__device__ int g_is64;

__device__ __forceinline__ float* buf_ptr(int s) {
    switch (s) {
        case 3: return g_u1;
        case 4: return g_u2;
        default: return g_h;
    }
}

// ---------------- preproc 1: edge dtype detect (block 0) + zero counts ----------------
__global__ void k_pre1(const int* __restrict__ v) {
    if (blockIdx.x == 0) {
        __shared__ int any;
        if (threadIdx.x == 0) any = 0;
        __syncthreads();
        int acc = 0;
        for (int i = threadIdx.x; i < 8192; i += 256) {
            int idx = i * 64 + 1;            // odd word, < 2*E
            acc |= v[idx];
        }
        if (acc) atomicOr(&any, 1);
        __syncthreads();
        if (threadIdx.x == 0) g_is64 = (any == 0) ? 1 : 0;
    } else {
        int i = (blockIdx.x - 1) * 256 + threadIdx.x;
        g_cnt[i] = 0;
    }
}

__device__ __forceinline__ int edge_at(const void* ei, int idx) {
    int v;
    if (g_is64) v = (int)((const long long*)ei)[idx];
    else        v = ((const int*)ei)[idx];
    return v & (N_NODES - 1);
}

__global__ void k_deg(const void* __restrict__ ei) {
    int e = blockIdx.x * blockDim.x + threadIdx.x;
    if (e < N_EDGES) atomicAdd(&g_cnt[edge_at(ei, N_EDGES + e)], 1);
}

// scan (1 block) + dis computation fused
__global__ void k_scan_dis() {
    __shared__ int part[1024];
    int t = threadIdx.x;
    int base = t * 8;
    int loc[8];
    int s = 0;
#pragma unroll
    for (int i = 0; i < 8; i++) {
        loc[i] = g_cnt[base + i];
        g_dis[base + i] = rsqrtf((float)loc[i] + 1.0f);
        s += loc[i];
    }
    part[t] = s;
    __syncthreads();
    for (int off = 1; off < 1024; off <<= 1) {
        int v = 0;
        if (t >= off) v = part[t - off];
        __syncthreads();
        part[t] += v;
        __syncthreads();
    }
    int run = part[t] - s;
#pragma unroll
    for (int i = 0; i < 8; i++) {
        g_off[base + i] = run;
        g_cur[base + i] = run;
        run += loc[i];
    }
}

__global__ void k_fill(const void* __restrict__ ei) {
    int e = blockIdx.x * blockDim.x + threadIdx.x;
    if (e < N_EDGES) {
        int s = edge_at(ei, e);
        int d = edge_at(ei, N_EDGES + e);
        float w = g_dis[s] * g_dis[d];
        int p = atomicAdd(&g_cur[d], 1);
        if (p < N_EDGES) g_csr[p] = make_int2(s, __float_as_int(w));
    }
}

// ---------------- fp16-gather agg: one warp per node, mirror input ----------------
__device__ __forceinline__ float4 agg_node16(const uint2* __restrict__ H2,
                                             int node, int lane,
                                             float4 bb, int relu) {
    float  di = g_dis[node];
    float  dd = di * di;
    uint2  hv = H2[(size_t)node * 32 + lane];
    float2 f01 = __half22float2(*(__half2*)&hv.x);
    float2 f23 = __half22float2(*(__half2*)&hv.y);
    float4 acc;
    acc.x = fmaf(f01.x, dd, bb.x);
    acc.y = fmaf(f01.y, dd, bb.y);
    acc.z = fmaf(f23.x, dd, bb.z);
    acc.w = fmaf(f23.y, dd, bb.w);
    float4 acc2 = make_float4(0.f, 0.f, 0.f, 0.f);

    int start = g_off[node];
    int cnt   = g_cnt[node];
    int j = 0;
    for (; j + 1 < cnt; j += 2) {
        int2 e0 = g_csr[start + j];
        int2 e1 = g_csr[start + j + 1];
        float w0 = __int_as_float(e0.y);
        float w1 = __int_as_float(e1.y);
        uint2 v0 = H2[(size_t)e0.x * 32 + lane];
        uint2 v1 = H2[(size_t)e1.x * 32 + lane];
        float2 a01 = __half22float2(*(__half2*)&v0.x);
        float2 a23 = __half22float2(*(__half2*)&v0.y);
        float2 b01 = __half22float2(*(__half2*)&v1.x);
        float2 b23 = __half22float2(*(__half2*)&v1.y);
        acc.x  = fmaf(a01.x, w0, acc.x);  acc.y  = fmaf(a01.y, w0, acc.y);
        acc.z  = fmaf(a23.x, w0, acc.z);  acc.w  = fmaf(a23.y, w0, acc.w);
        acc2.x = fmaf(b01.x, w1, acc2.x); acc2.y = fmaf(b01.y, w1, acc2.y);
        acc2.z = fmaf(b23.x, w1, acc2.z); acc2.w = fmaf(b23.y, w1, acc2.w);
    }
    if (j < cnt) {
        int2 e0 = g_csr[start + j];
        float w0 = __int_as_float(e0.y);
        uint2 v0 = H2[(size_t)e0.x * 32 + lane];
        float2 a01 = __half22float2(*(__half2*)&v0.x);
        float2 a23 = __half22float2(*(__half2*)&v0.y);
        acc.x = fmaf(a01.x, w0, acc.x); acc.y = fmaf(a01.y, w0, acc.y);
        acc.z = fmaf(a23.x, w0, acc.z); acc.w = fmaf(a23.y, w0, acc.w);
    }
    acc.x += acc2.x; acc.y += acc2.y; acc.z += acc2.z; acc.w += acc2.w;
    if (relu) {
        acc.x = fmaxf(acc.x, 0.f); acc.y = fmaxf(acc.y, 0.f);
        acc.z = fmaxf(acc.z, 0.f); acc.w = fmaxf(acc.w, 0.f);
    }
    return acc;
}

// ---------------- epilogue helper: 8 fp32 -> 8 fp16 (one uint4 store) ----------------
__device__ __forceinline__ void store_h16(__half* dst, const float* v) {
    __half tmp[8];
#pragma unroll
    for (int i = 0; i < 8; i++) tmp[i] = __float2half_rn(v[i]);
    *(uint4*)dst = *(uint4*)tmp;
}

// ---------------- dense GEMM (NodeModel): g_h = buf_ptr(selA) @ W, + g_h16 mirror ----------------
__global__ __launch_bounds__(256) void k_gemm_small(int selA,
                                                    const float* __restrict__ W) {
    __shared__ float Wsm[32 * 128];
    __shared__ float Asm[64 * 40];

    const float* A = buf_ptr(selA);
    int tid = threadIdx.x;
    int rb  = blockIdx.x * 64;
    int cg = tid & 15, rg = tid >> 4;
    int r0 = rg * 4, c0 = cg * 8;

    float acc[4][8];
#pragma unroll
    for (int i = 0; i < 4; i++)
#pragma unroll
        for (int j = 0; j < 8; j++) acc[i][j] = 0.f;

    for (int c = 0; c < 4; c++) {
        int kc0 = c * 32;
        __syncthreads();
#pragma unroll
        for (int i = 0; i < 4; i++) {
            int idx = tid + i * 256;
            int k = idx >> 5, c4 = idx & 31;
            *(float4*)&Wsm[k * 128 + c4 * 4] =
                *(const float4*)&W[(size_t)(kc0 + k) * 128 + c4 * 4];
        }
#pragma unroll
        for (int i = 0; i < 2; i++) {
            int idx = tid + i * 256;
            int row = idx >> 3, c4 = idx & 7;
            *(float4*)&Asm[row * 40 + c4 * 4] =
                *(const float4*)&A[(size_t)(rb + row) * 128 + kc0 + c4 * 4];
        }
        __syncthreads();

#pragma unroll
        for (int k = 0; k < 32; k += 4) {
            float4 a[4];
#pragma unroll
            for (int i = 0; i < 4; i++) a[i] = *(const float4*)&Asm[(r0 + i) * 40 + k];
#pragma unroll
            for (int kk = 0; kk < 4; kk++) {
                float4 bLo = *(const float4*)&Wsm[(k + kk) * 128 + c0];
                float4 bHi = *(const float4*)&Wsm[(k + kk) * 128 + c0 + 4];
                float bv[8] = {bLo.x, bLo.y, bLo.z, bLo.w, bHi.x, bHi.y, bHi.z, bHi.w};
#pragma unroll
                for (int i = 0; i < 4; i++) {
                    float av = (kk == 0) ? a[i].x : (kk == 1) ? a[i].y
                               : (kk == 2) ? a[i].z : a[i].w;
#pragma unroll
                    for (int j = 0; j < 8; j++)
                        acc[i][j] = fmaf(av, bv[j], acc[i][j]);
                }
            }
        }
    }

#pragma unroll
    for (int i = 0; i < 4; i++) {
        float4 lo = make_float4(acc[i][0], acc[i][1], acc[i][2], acc[i][3]);
        float4 hi = make_float4(acc[i][4], acc[i][5], acc[i][6], acc[i][7]);
        size_t base = (size_t)(rb + r0 + i) * 128 + c0;
        *(float4*)&g_h[base]     = lo;
        *(float4*)&g_h[base + 4] = hi;
        store_h16(&g_h16[base], acc[i]);
    }
}

// ---------------- k_gemm_x3: x @ {Ws, Wt, W1}; writes fp16 mirrors ----------------
__global__ __launch_bounds__(256) void k_gemm_x3(const float* __restrict__ x,
                                                 const float* __restrict__ Ws,
                                                 const float* __restrict__ Wt,
                                                 const float* __restrict__ W1) {
    __shared__ float Wsm[32 * 128];
    __shared__ float Asm[64 * 40];

    const float* W;
    __half* M16;
    float*  Ofp = nullptr;
    if (blockIdx.y == 0)      { W = Ws; M16 = g_s16; }
    else if (blockIdx.y == 1) { W = Wt; M16 = g_t16; }
    else                      { W = W1; M16 = g_h16; Ofp = g_h; }

    int tid = threadIdx.x;
    int rb  = blockIdx.x * 64;
    int cg = tid & 15, rg = tid >> 4;
    int r0 = rg * 4, c0 = cg * 8;

    float acc[4][8];
#pragma unroll
    for (int i = 0; i < 4; i++)
#pragma unroll
        for (int j = 0; j < 8; j++) acc[i][j] = 0.f;

    for (int c = 0; c < 4; c++) {
        int kc0 = c * 32;
        __syncthreads();
#pragma unroll
        for (int i = 0; i < 4; i++) {
            int idx = tid + i * 256;
            int k = idx >> 5, c4 = idx & 31;
            *(float4*)&Wsm[k * 128 + c4 * 4] =
                *(const float4*)&W[(size_t)(kc0 + k) * 128 + c4 * 4];
        }
#pragma unroll
        for (int i = 0; i < 2; i++) {
            int idx = tid + i * 256;
            int row = idx >> 3, c4 = idx & 7;
            *(float4*)&Asm[row * 40 + c4 * 4] =
                *(const float4*)&x[(size_t)(rb + row) * 128 + kc0 + c4 * 4];
        }
        __syncthreads();

#pragma unroll
        for (int k = 0; k < 32; k += 4) {
            float4 a[4];
#pragma unroll
            for (int i = 0; i < 4; i++) a[i] = *(const float4*)&Asm[(r0 + i) * 40 + k];
#pragma unroll
            for (int kk = 0; kk < 4; kk++) {
                float4 bLo = *(const float4*)&Wsm[(k + kk) * 128 + c0];
                float4 bHi = *(const float4*)&Wsm[(k + kk) * 128 + c0 + 4];
                float bv[8] = {bLo.x, bLo.y, bLo.z, bLo.w, bHi.x, bHi.y, bHi.z, bHi.w};
#pragma unroll
                for (int i = 0; i < 4; i++) {
                    float av = (kk == 0) ? a[i].x : (kk == 1) ? a[i].y
                               : (kk == 2) ? a[i].z : a[i].w;
#pragma unroll
                    for (int j = 0; j < 8; j++)
                        acc[i][j] = fmaf(av, bv[j], acc[i][j]);
                }
            }
        }
    }

#pragma unroll
    for (int i = 0; i < 4; i++) {
        size_t base = (size_t)(rb + r0 + i) * 128 + c0;
        store_h16(&M16[base], acc[i]);
        if (Ofp) {
            float4 lo = make_float4(acc[i][0], acc[i][1], acc[i][2], acc[i][3]);
            float4 hi = make_float4(acc[i][4], acc[i][5], acc[i][6], acc[i][7]);
            *(float4*)&Ofp[base]     = lo;
            *(float4*)&Ofp[base + 4] = hi;
        }
    }
}

// ---------------- GCN aggregation (1024 blocks): fp16 gather from g_h16 ----------------
__global__ __launch_bounds__(256) void k_agg(const float* __restrict__ bias,
                                             float* __restrict__ Oext, int selO,
                                             int relu) {
    float* O = Oext ? Oext : buf_ptr(selO);
    const uint2* H2 = (const uint2*)g_h16;
    int warp = threadIdx.x >> 5, lane = threadIdx.x & 31;
    int node = blockIdx.x * 8 + warp;
    float4 bb = ((const float4*)bias)[lane];
    float4 acc = agg_node16(H2, node, lane, bb, relu);
    ((float4*)O)[(size_t)node * 32 + lane] = acc;
}

// ---------------- k_agg_st (2048 blocks): fp16 gather, write decoder packs ----------------
__global__ __launch_bounds__(256) void k_agg_st(const float* __restrict__ bs,
                                                const float* __restrict__ bt) {
    int warp = threadIdx.x >> 5, lane = threadIdx.x & 31;
    int smode = (blockIdx.x < 1024);
    int node = (smode ? blockIdx.x : blockIdx.x - 1024) * 8 + warp;
    const uint2* H2 = (const uint2*)(smode ? g_s16 : g_t16);
    const float* bias = smode ? bs : bt;

    float4 bb = ((const float4*)bias)[lane];
    float4 acc = agg_node16(H2, node, lane, bb, 0);

    __half p0 = __float2half_rn(acc.x), p1 = __float2half_rn(acc.y);
    __half p2 = __float2half_rn(acc.z), p3 = __float2half_rn(acc.w);
    __half pk[4] = {p0, p1, p2, p3};
    size_t pb = (size_t)node * KPACK + lane * 4;
    if (smode) *(uint2*)&g_apack[pb] = *(uint2*)pk;
    else       *(uint2*)&g_bpack[pb] = *(uint2*)pk;
}

// ---------------- HMMA decoder: adj = Apack @ Bpack^T (fp16, K=128) ----------------
__device__ __forceinline__ void ldsm_x4(uint32_t& r0, uint32_t& r1,
                                        uint32_t& r2, uint32_t& r3, uint32_t a) {
    asm volatile("ldmatrix.sync.aligned.m8n8.x4.shared.b16 {%0,%1,%2,%3}, [%4];"
                 : "=r"(r0), "=r"(r1), "=r"(r2), "=r"(r3) : "r"(a));
}
__device__ __forceinline__ void mma_f16(float& c0, float& c1, float& c2, float& c3,
                                        uint32_t a0, uint32_t a1, uint32_t a2, uint32_t a3,
                                        uint32_t b0, uint32_t b1) {
    asm volatile(
        "mma.sync.aligned.m16n8k16.row.col.f32.f16.f16.f32 "
        "{%0,%1,%2,%3}, {%4,%5,%6,%7}, {%8,%9}, {%0,%1,%2,%3};"
        : "+f"(c0), "+f"(c1), "+f"(c2), "+f"(c3)
        : "r"(a0), "r"(a1), "r"(a2), "r"(a3), "r"(b0), "r"(b1));
}
__device__ __forceinline__ void cp_async16(uint32_t dst, const void* src) {
    asm volatile("cp.async.cg.shared.global [%0], [%1], 16;" :: "r"(dst), "l"(src));
}
#define CP_COMMIT() asm volatile("cp.async.commit_group;" ::: "memory")
#define CP_WAIT(n)  asm volatile("cp.async.wait_group %0;" :: "n"(n) : "memory")
#define SWZ(off) ((off) ^ (((off) >> 3) & 0x70))

#define A_BYTES   32768        // 256 rows x 128B (Kc=64 halves)
#define B_BYTES   16384        // 128 rows x 128B
#define BUF_BYTES (A_BYTES + B_BYTES)
#define DEC_SMEM  (2 * BUF_BYTES)   // 96 KB

__global__ __launch_bounds__(256) void k_decoder(float* __restrict__ adj) {
    extern __shared__ __align__(16) char smem[];
    uint32_t sbase = (uint32_t)__cvta_generic_to_shared(smem);

    int tid  = threadIdx.x;
    int wid  = tid >> 5, lane = tid & 31;
    int wm   = wid >> 1, wn = wid & 1;        // 4 x 2 warp grid, warp tile m64 n64
    int cb   = blockIdx.x * 128;              // N offset
    int rb   = blockIdx.y * 256;              // M offset

    float acc[4][8][4];
#pragma unroll
    for (int m = 0; m < 4; m++)
#pragma unroll
        for (int n = 0; n < 8; n++)
#pragma unroll
            for (int r = 0; r < 4; r++) acc[m][n][r] = 0.f;

#define LOAD_CHUNK(c, buf) do {                                                  \
    int kc0 = (c) * 64;                                                          \
    uint32_t base = sbase + (buf) * BUF_BYTES;                                   \
    _Pragma("unroll")                                                            \
    for (int i = 0; i < 12; i++) {                                               \
        int seg = tid + i * 256;                                                 \
        if (seg < 2048) {                                                        \
            int row = seg >> 3, sgi = seg & 7;                                   \
            uint32_t off = (uint32_t)(row * 128 + sgi * 16);                     \
            cp_async16(base + SWZ(off),                                          \
                       &g_apack[(size_t)(rb + row) * KPACK + kc0 + sgi * 8]);    \
        } else {                                                                 \
            int bseg = seg - 2048;                                               \
            int row = bseg >> 3, sgi = bseg & 7;                                 \
            uint32_t off = (uint32_t)(row * 128 + sgi * 16);                     \
            cp_async16(base + A_BYTES + SWZ(off),                                \
                       &g_bpack[(size_t)(cb + row) * KPACK + kc0 + sgi * 8]);    \
        }                                                                        \
    }                                                                            \
} while (0)

    LOAD_CHUNK(0, 0);
    CP_COMMIT();

#pragma unroll 1
    for (int c = 0; c < 2; c++) {
        int buf = c & 1;
        if (c < 1) {
            LOAD_CHUNK(c + 1, buf ^ 1);
            CP_COMMIT();
            CP_WAIT(1);
        } else {
            CP_WAIT(0);
        }
        __syncthreads();

        uint32_t abase = sbase + buf * BUF_BYTES;
        uint32_t bbase = abase + A_BYTES;
#pragma unroll
        for (int ks = 0; ks < 4; ks++) {
            uint32_t a[4][4], b[4][4];
#pragma unroll
            for (int mt = 0; mt < 4; mt++) {
                int row = wm * 64 + mt * 16 + (lane & 15);
                uint32_t off = (uint32_t)(row * 128 + ks * 32 + ((lane >> 4) & 1) * 16);
                ldsm_x4(a[mt][0], a[mt][1], a[mt][2], a[mt][3], abase + SWZ(off));
            }
#pragma unroll
            for (int nt = 0; nt < 4; nt++) {
                int row = wn * 64 + nt * 16 + (lane & 15);
                uint32_t off = (uint32_t)(row * 128 + ks * 32 + ((lane >> 4) & 1) * 16);
                ldsm_x4(b[nt][0], b[nt][1], b[nt][2], b[nt][3], bbase + SWZ(off));
            }
#pragma unroll
            for (int mt = 0; mt < 4; mt++)
#pragma unroll
                for (int nt = 0; nt < 4; nt++) {
                    mma_f16(acc[mt][nt * 2][0], acc[mt][nt * 2][1],
                            acc[mt][nt * 2][2], acc[mt][nt * 2][3],
                            a[mt][0], a[mt][1], a[mt][2], a[mt][3],
                            b[nt][0], b[nt][2]);
                    mma_f16(acc[mt][nt * 2 + 1][0], acc[mt][nt * 2 + 1][1],
                            acc[mt][nt * 2 + 1][2], acc[mt][nt * 2 + 1][3],
                            a[mt][0], a[mt][1], a[mt][2], a[mt][3],
                            b[nt][1], b[nt][3]);
                }
        }
        __syncthreads();
    }

#pragma unroll
    for (int mt = 0; mt < 4; mt++) {
#pragma unroll
        for (int nt = 0; nt < 8; nt++) {
            int row = rb + wm * 64 + mt * 16 + (lane >> 2);
            int col = cb + wn * 64 + nt * 8 + (lane & 3) * 2;
            *(float2*)&adj[(size_t)row * 8192 + col] =
                make_float2(acc[mt][nt][0], acc[mt][nt][1]);
            *(float2*)&adj[(size_t)(row + 8) * 8192 + col] =
                make_float2(acc[mt][nt][2], acc[mt][nt][3]);
        }
    }
}

// ---------------- launch: round-12 two-arm schedule + fp16 gather ----------------
extern "C" void kernel_launch(void* const* d_in, const int* in_sizes, int n_in,
                              void* d_out, int out_size) {
    (void)in_sizes; (void)n_in;
    const float* x  = (const float*)d_in[0];
    const void*  ei = d_in[1];
    const float *Ws = (const float*)d_in[2],  *bs  = (const float*)d_in[3];
    const float *Wt = (const float*)d_in[4],  *bt  = (const float*)d_in[5];
    const float *W1 = (const float*)d_in[6],  *b1  = (const float*)d_in[7];
    const float *W2 = (const float*)d_in[8],  *b2  = (const float*)d_in[9];
    const float *Wmu= (const float*)d_in[10], *bmu = (const float*)d_in[11];
    const float *W5 = (const float*)d_in[12], *b5  = (const float*)d_in[13];
    const float *W6 = (const float*)d_in[14], *b6  = (const float*)d_in[15];

    float* adj  = (float*)d_out;
    float* hout = (float*)d_out + ((size_t)out_size - (size_t)N_NODES * C_CH);

    cudaFuncSetAttribute(k_decoder, cudaFuncAttributeMaxDynamicSharedMemorySize,
                         DEC_SMEM);

    cudaStream_t sB;
    cudaStreamCreateWithFlags(&sB, cudaStreamNonBlocking);
    cudaEvent_t evStart, evPre, evX, evB;
    cudaEventCreateWithFlags(&evStart, cudaEventDisableTiming);
    cudaEventCreateWithFlags(&evPre,   cudaEventDisableTiming);
    cudaEventCreateWithFlags(&evX,     cudaEventDisableTiming);
    cudaEventCreateWithFlags(&evB,     cudaEventDisableTiming);

    // ---- fork ----
    cudaEventRecord(evStart, 0);
    cudaStreamWaitEvent(sB, evStart, 0);

    // ---- side stream: preprocessing (needs only ei) ----
    k_pre1<<<33, 256, 0, sB>>>((const int*)ei);
    k_deg<<<N_EDGES / 256, 256, 0, sB>>>(ei);
    k_scan_dis<<<1, 1024, 0, sB>>>();
    k_fill<<<N_EDGES / 256, 256, 0, sB>>>(ei);
    cudaEventRecord(evPre, sB);

    // ---- main stream: x @ {Ws, Wt, W1} (needs only x), overlapped with preproc ----
    k_gemm_x3<<<dim3(128, 3), 256>>>(x, Ws, Wt, W1);
    cudaEventRecord(evX, 0);

    // ---- side stream: NodeModel chain (unfused, fp16 gather) ----
    cudaStreamWaitEvent(sB, evX, 0);
    k_agg<<<1024, 256, 0, sB>>>(b1,  nullptr, 3, 1);      // g_h16 -> u1
    k_gemm_small<<<128, 256, 0, sB>>>(3, W2);             // u1 -> g_h + g_h16
    k_agg<<<1024, 256, 0, sB>>>(b2,  nullptr, 4, 1);      // -> u2
    k_gemm_small<<<128, 256, 0, sB>>>(4, Wmu);
    k_agg<<<1024, 256, 0, sB>>>(bmu, nullptr, 3, 0);      // -> u1 (no relu)
    k_gemm_small<<<128, 256, 0, sB>>>(3, W5);
    k_agg<<<1024, 256, 0, sB>>>(b5,  nullptr, 4, 1);      // -> u2
    k_gemm_small<<<128, 256, 0, sB>>>(4, W6);
    k_agg<<<1024, 256, 0, sB>>>(b6,  hout,    0, 1);      // -> hout
    cudaEventRecord(evB, sB);

    // ---- main stream: s/t agg + packs (needs preproc + gemm_x3), then decoder ----
    cudaStreamWaitEvent(0, evPre, 0);
    k_agg_st<<<2048, 256>>>(bs, bt);
    k_decoder<<<dim3(64, 32), 256, DEC_SMEM>>>(adj);

    // ---- join ----
    cudaStreamWaitEvent(0, evB, 0);
}

// round 15
// speedup vs baseline: 1.1433x; 1.0707x over previous
#include <cuda_runtime.h>
#include <cuda_fp16.h>
#include <cstdint>

#define N_NODES 8192
#define C_CH    128
#define N_EDGES 262144
#define KPACK   128            // single fp16 product: K = C

// ---------------- scratch (device globals; no allocation allowed) ----------------
__device__ __align__(16) float g_dis[N_NODES];
__device__ __align__(16) int   g_cnt[N_NODES];
__device__ __align__(16) int   g_off[N_NODES];
__device__ __align__(16) int   g_cur[N_NODES];
__device__ __align__(16) int2  g_csr[N_EDGES];
__device__ __align__(16) float g_h  [N_NODES * C_CH];   // NodeModel gemm scratch
__device__ __align__(16) float g_s  [N_NODES * C_CH];   // pre-agg x@Ws
__device__ __align__(16) float g_t  [N_NODES * C_CH];   // pre-agg x@Wt
__device__ __align__(16) float g_u1 [N_NODES * C_CH];
__device__ __align__(16) float g_u2 [N_NODES * C_CH];
// packed fp16 decoder operands: A=Sh, B=Th
__device__ __align__(16) __half g_apack[N_NODES * KPACK];
__device__ __align__(16) __half g_bpack[N_NODES * KPACK];
__device__ int g_is64;

__device__ __forceinline__ float* buf_ptr(int s) {
    switch (s) {
        case 1: return g_s;
        case 2: return g_t;
        case 3: return g_u1;
        case 4: return g_u2;
        default: return g_h;
    }
}

// ---------------- preproc 1: edge dtype detect (block 0) + zero counts ----------------
__global__ void k_pre1(const int* __restrict__ v) {
    if (blockIdx.x == 0) {
        __shared__ int any;
        if (threadIdx.x == 0) any = 0;
        __syncthreads();
        int acc = 0;
        for (int i = threadIdx.x; i < 8192; i += 256) {
            int idx = i * 64 + 1;            // odd word, < 2*E
            acc |= v[idx];
        }
        if (acc) atomicOr(&any, 1);
        __syncthreads();
        if (threadIdx.x == 0) g_is64 = (any == 0) ? 1 : 0;
    } else {
        int i = (blockIdx.x - 1) * 256 + threadIdx.x;
        g_cnt[i] = 0;
    }
}

__device__ __forceinline__ int edge_at(const void* ei, int idx) {
    int v;
    if (g_is64) v = (int)((const long long*)ei)[idx];
    else        v = ((const int*)ei)[idx];
    return v & (N_NODES - 1);
}

__global__ void k_deg(const void* __restrict__ ei) {
    int e = blockIdx.x * blockDim.x + threadIdx.x;
    if (e < N_EDGES) atomicAdd(&g_cnt[edge_at(ei, N_EDGES + e)], 1);
}

// scan (1 block) + dis computation fused
__global__ void k_scan_dis() {
    __shared__ int part[1024];
    int t = threadIdx.x;
    int base = t * 8;
    int loc[8];
    int s = 0;
#pragma unroll
    for (int i = 0; i < 8; i++) {
        loc[i] = g_cnt[base + i];
        g_dis[base + i] = rsqrtf((float)loc[i] + 1.0f);
        s += loc[i];
    }
    part[t] = s;
    __syncthreads();
    for (int off = 1; off < 1024; off <<= 1) {
        int v = 0;
        if (t >= off) v = part[t - off];
        __syncthreads();
        part[t] += v;
        __syncthreads();
    }
    int run = part[t] - s;
#pragma unroll
    for (int i = 0; i < 8; i++) {
        g_off[base + i] = run;
        g_cur[base + i] = run;
        run += loc[i];
    }
}

__global__ void k_fill(const void* __restrict__ ei) {
    int e = blockIdx.x * blockDim.x + threadIdx.x;
    if (e < N_EDGES) {
        int s = edge_at(ei, e);
        int d = edge_at(ei, N_EDGES + e);
        float w = g_dis[s] * g_dis[d];
        int p = atomicAdd(&g_cur[d], 1);
        if (p < N_EDGES) g_csr[p] = make_int2(s, __float_as_int(w));
    }
}

// ---------------- shared agg routine: one warp aggregates one node ----------------
__device__ __forceinline__ float4 agg_node(const float4* __restrict__ H4,
                                           int node, int lane,
                                           float4 bb, int relu) {
    float  di = g_dis[node];
    float  dd = di * di;
    float4 h  = H4[(size_t)node * 32 + lane];
    float4 acc;
    acc.x = fmaf(h.x, dd, bb.x);
    acc.y = fmaf(h.y, dd, bb.y);
    acc.z = fmaf(h.z, dd, bb.z);
    acc.w = fmaf(h.w, dd, bb.w);
    float4 acc2 = make_float4(0.f, 0.f, 0.f, 0.f);

    int start = g_off[node];
    int cnt   = g_cnt[node];
    int j = 0;
    for (; j + 1 < cnt; j += 2) {
        int2 e0 = g_csr[start + j];
        int2 e1 = g_csr[start + j + 1];
        float w0 = __int_as_float(e0.y);
        float w1 = __int_as_float(e1.y);
        float4 v0 = H4[(size_t)e0.x * 32 + lane];
        float4 v1 = H4[(size_t)e1.x * 32 + lane];
        acc.x  = fmaf(v0.x, w0, acc.x);  acc.y  = fmaf(v0.y, w0, acc.y);
        acc.z  = fmaf(v0.z, w0, acc.z);  acc.w  = fmaf(v0.w, w0, acc.w);
        acc2.x = fmaf(v1.x, w1, acc2.x); acc2.y = fmaf(v1.y, w1, acc2.y);
        acc2.z = fmaf(v1.z, w1, acc2.z); acc2.w = fmaf(v1.w, w1, acc2.w);
    }
    if (j < cnt) {
        int2 e0 = g_csr[start + j];
        float w0 = __int_as_float(e0.y);
        float4 v0 = H4[(size_t)e0.x * 32 + lane];
        acc.x = fmaf(v0.x, w0, acc.x); acc.y = fmaf(v0.y, w0, acc.y);
        acc.z = fmaf(v0.z, w0, acc.z); acc.w = fmaf(v0.w, w0, acc.w);
    }
    acc.x += acc2.x; acc.y += acc2.y; acc.z += acc2.z; acc.w += acc2.w;
    if (relu) {
        acc.x = fmaxf(acc.x, 0.f); acc.y = fmaxf(acc.y, 0.f);
        acc.z = fmaxf(acc.z, 0.f); acc.w = fmaxf(acc.w, 0.f);
    }
    return acc;
}

// ---------------- dense GEMM: buf_ptr(outSel) = buf_ptr(selA) @ W (NodeModel) ----------------
__global__ __launch_bounds__(256) void k_gemm_small(int selA,
                                                    const float* __restrict__ W,
                                                    int outSel) {
    __shared__ float Wsm[32 * 128];
    __shared__ float Asm[64 * 40];

    const float* A = buf_ptr(selA);
    float* Ob = buf_ptr(outSel);
    int tid = threadIdx.x;
    int rb  = blockIdx.x * 64;
    int cg = tid & 15, rg = tid >> 4;
    int r0 = rg * 4, c0 = cg * 8;

    float acc[4][8];
#pragma unroll
    for (int i = 0; i < 4; i++)
#pragma unroll
        for (int j = 0; j < 8; j++) acc[i][j] = 0.f;

    for (int c = 0; c < 4; c++) {
        int kc0 = c * 32;
        __syncthreads();
#pragma unroll
        for (int i = 0; i < 4; i++) {
            int idx = tid + i * 256;
            int k = idx >> 5, c4 = idx & 31;
            *(float4*)&Wsm[k * 128 + c4 * 4] =
                *(const float4*)&W[(size_t)(kc0 + k) * 128 + c4 * 4];
        }
#pragma unroll
        for (int i = 0; i < 2; i++) {
            int idx = tid + i * 256;
            int row = idx >> 3, c4 = idx & 7;
            *(float4*)&Asm[row * 40 + c4 * 4] =
                *(const float4*)&A[(size_t)(rb + row) * 128 + kc0 + c4 * 4];
        }
        __syncthreads();

#pragma unroll
        for (int k = 0; k < 32; k += 4) {
            float4 a[4];
#pragma unroll
            for (int i = 0; i < 4; i++) a[i] = *(const float4*)&Asm[(r0 + i) * 40 + k];
#pragma unroll
            for (int kk = 0; kk < 4; kk++) {
                float4 bLo = *(const float4*)&Wsm[(k + kk) * 128 + c0];
                float4 bHi = *(const float4*)&Wsm[(k + kk) * 128 + c0 + 4];
                float bv[8] = {bLo.x, bLo.y, bLo.z, bLo.w, bHi.x, bHi.y, bHi.z, bHi.w};
#pragma unroll
                for (int i = 0; i < 4; i++) {
                    float av = (kk == 0) ? a[i].x : (kk == 1) ? a[i].y
                               : (kk == 2) ? a[i].z : a[i].w;
#pragma unroll
                    for (int j = 0; j < 8; j++)
                        acc[i][j] = fmaf(av, bv[j], acc[i][j]);
                }
            }
        }
    }

#pragma unroll
    for (int i = 0; i < 4; i++) {
        float4 lo = make_float4(acc[i][0], acc[i][1], acc[i][2], acc[i][3]);
        float4 hi = make_float4(acc[i][4], acc[i][5], acc[i][6], acc[i][7]);
        size_t base = (size_t)(rb + r0 + i) * 128 + c0;
        *(float4*)&Ob[base]     = lo;
        *(float4*)&Ob[base + 4] = hi;
    }
}

// ---------------- k_gemm_x3: x @ {Ws, Wt, W1} in one launch (gridDim.y=3) ----------------
__global__ __launch_bounds__(256) void k_gemm_x3(const float* __restrict__ x,
                                                 const float* __restrict__ Ws,
                                                 const float* __restrict__ Wt,
                                                 const float* __restrict__ W1) {
    __shared__ float Wsm[32 * 128];
    __shared__ float Asm[64 * 40];

    const float* W;
    float* Ob;
    if (blockIdx.y == 0)      { W = Ws; Ob = g_s; }
    else if (blockIdx.y == 1) { W = Wt; Ob = g_t; }
    else                      { W = W1; Ob = g_h; }

    int tid = threadIdx.x;
    int rb  = blockIdx.x * 64;
    int cg = tid & 15, rg = tid >> 4;
    int r0 = rg * 4, c0 = cg * 8;

    float acc[4][8];
#pragma unroll
    for (int i = 0; i < 4; i++)
#pragma unroll
        for (int j = 0; j < 8; j++) acc[i][j] = 0.f;

    for (int c = 0; c < 4; c++) {
        int kc0 = c * 32;
        __syncthreads();
#pragma unroll
        for (int i = 0; i < 4; i++) {
            int idx = tid + i * 256;
            int k = idx >> 5, c4 = idx & 31;
            *(float4*)&Wsm[k * 128 + c4 * 4] =
                *(const float4*)&W[(size_t)(kc0 + k) * 128 + c4 * 4];
        }
#pragma unroll
        for (int i = 0; i < 2; i++) {
            int idx = tid + i * 256;
            int row = idx >> 3, c4 = idx & 7;
            *(float4*)&Asm[row * 40 + c4 * 4] =
                *(const float4*)&x[(size_t)(rb + row) * 128 + kc0 + c4 * 4];
        }
        __syncthreads();

#pragma unroll
        for (int k = 0; k < 32; k += 4) {
            float4 a[4];
#pragma unroll
            for (int i = 0; i < 4; i++) a[i] = *(const float4*)&Asm[(r0 + i) * 40 + k];
#pragma unroll
            for (int kk = 0; kk < 4; kk++) {
                float4 bLo = *(const float4*)&Wsm[(k + kk) * 128 + c0];
                float4 bHi = *(const float4*)&Wsm[(k + kk) * 128 + c0 + 4];
                float bv[8] = {bLo.x, bLo.y, bLo.z, bLo.w, bHi.x, bHi.y, bHi.z, bHi.w};
#pragma unroll
                for (int i = 0; i < 4; i++) {
                    float av = (kk == 0) ? a[i].x : (kk == 1) ? a[i].y
                               : (kk == 2) ? a[i].z : a[i].w;
#pragma unroll
                    for (int j = 0; j < 8; j++)
                        acc[i][j] = fmaf(av, bv[j], acc[i][j]);
                }
            }
        }
    }

#pragma unroll
    for (int i = 0; i < 4; i++) {
        float4 lo = make_float4(acc[i][0], acc[i][1], acc[i][2], acc[i][3]);
        float4 hi = make_float4(acc[i][4], acc[i][5], acc[i][6], acc[i][7]);
        size_t base = (size_t)(rb + r0 + i) * 128 + c0;
        *(float4*)&Ob[base]     = lo;
        *(float4*)&Ob[base + 4] = hi;
    }
}

// ---------------- GCN aggregation (1024 blocks): reads buf_ptr(inSel) ----------------
__global__ __launch_bounds__(256) void k_agg(const float* __restrict__ bias,
                                             float* __restrict__ Oext, int selO,
                                             int relu, int inSel) {
    float* O = Oext ? Oext : buf_ptr(selO);
    const float4* H4 = (const float4*)buf_ptr(inSel);
    int warp = threadIdx.x >> 5, lane = threadIdx.x & 31;
    int node = blockIdx.x * 8 + warp;
    float4 bb = ((const float4*)bias)[lane];
    float4 acc = agg_node(H4, node, lane, bb, relu);
    ((float4*)O)[(size_t)node * 32 + lane] = acc;
}

// ---------------- k_agg_st (2048 blocks): agg s and t + write fp16 packs ----------------
__global__ __launch_bounds__(256) void k_agg_st(const float* __restrict__ bs,
                                                const float* __restrict__ bt) {
    int warp = threadIdx.x >> 5, lane = threadIdx.x & 31;
    int smode = (blockIdx.x < 1024);
    int node = (smode ? blockIdx.x : blockIdx.x - 1024) * 8 + warp;
    const float4* H4 = (const float4*)(smode ? g_s : g_t);
    const float*  bias = smode ? bs : bt;

    float4 bb = ((const float4*)bias)[lane];
    float4 acc = agg_node(H4, node, lane, bb, 0);

    __half p0 = __float2half_rn(acc.x), p1 = __float2half_rn(acc.y);
    __half p2 = __float2half_rn(acc.z), p3 = __float2half_rn(acc.w);
    __half pk[4] = {p0, p1, p2, p3};
    size_t pb = (size_t)node * KPACK + lane * 4;
    if (smode) *(uint2*)&g_apack[pb] = *(uint2*)pk;
    else       *(uint2*)&g_bpack[pb] = *(uint2*)pk;
}

// ---------------- HMMA decoder: adj = Apack @ Bpack^T (fp16, K=128) ----------------
// Block 128x128, 8 warps (2m x 4n), warp tile m64 x n32, 2 CTAs/SM (regs<=128, smem 64KB)
__device__ __forceinline__ void ldsm_x4(uint32_t& r0, uint32_t& r1,
                                        uint32_t& r2, uint32_t& r3, uint32_t a) {
    asm volatile("ldmatrix.sync.aligned.m8n8.x4.shared.b16 {%0,%1,%2,%3}, [%4];"
                 : "=r"(r0), "=r"(r1), "=r"(r2), "=r"(r3) : "r"(a));
}
__device__ __forceinline__ void mma_f16(float& c0, float& c1, float& c2, float& c3,
                                        uint32_t a0, uint32_t a1, uint32_t a2, uint32_t a3,
                                        uint32_t b0, uint32_t b1) {
    asm volatile(
        "mma.sync.aligned.m16n8k16.row.col.f32.f16.f16.f32 "
        "{%0,%1,%2,%3}, {%4,%5,%6,%7}, {%8,%9}, {%0,%1,%2,%3};"
        : "+f"(c0), "+f"(c1), "+f"(c2), "+f"(c3)
        : "r"(a0), "r"(a1), "r"(a2), "r"(a3), "r"(b0), "r"(b1));
}
__device__ __forceinline__ void cp_async16(uint32_t dst, const void* src) {
    asm volatile("cp.async.cg.shared.global [%0], [%1], 16;" :: "r"(dst), "l"(src));
}
#define CP_COMMIT() asm volatile("cp.async.commit_group;" ::: "memory")
#define CP_WAIT(n)  asm volatile("cp.async.wait_group %0;" :: "n"(n) : "memory")
#define SWZ(off) ((off) ^ (((off) >> 3) & 0x70))

#define A_BYTES   16384        // 128 rows x 128B (Kc=64)
#define B_BYTES   16384        // 128 rows x 128B
#define BUF_BYTES (A_BYTES + B_BYTES)   // 32 KB
#define DEC_SMEM  (2 * BUF_BYTES)       // 64 KB

__global__ __launch_bounds__(256, 2) void k_decoder(float* __restrict__ adj) {
    extern __shared__ __align__(16) char smem[];
    uint32_t sbase = (uint32_t)__cvta_generic_to_shared(smem);

    int tid  = threadIdx.x;
    int wid  = tid >> 5, lane = tid & 31;
    int wm   = wid >> 2, wn = wid & 3;        // 2 x 4 warp grid, warp tile m64 n32
    int cb   = blockIdx.x * 128;              // N offset
    int rb   = blockIdx.y * 128;              // M offset

    float acc[4][4][4];                       // 4 m16-frags x 4 n8-frags x 4
#pragma unroll
    for (int m = 0; m < 4; m++)
#pragma unroll
        for (int n = 0; n < 4; n++)
#pragma unroll
            for (int r = 0; r < 4; r++) acc[m][n][r] = 0.f;

#define LOAD_CHUNK(c, buf) do {                                                  \
    int kc0 = (c) * 64;                                                          \
    uint32_t base = sbase + (buf) * BUF_BYTES;                                   \
    _Pragma("unroll")                                                            \
    for (int i = 0; i < 8; i++) {                                                \
        int seg = tid + i * 256;                                                 \
        if (seg < 1024) {                                                        \
            int row = seg >> 3, sgi = seg & 7;                                   \
            uint32_t off = (uint32_t)(row * 128 + sgi * 16);                     \
            cp_async16(base + SWZ(off),                                          \
                       &g_apack[(size_t)(rb + row) * KPACK + kc0 + sgi * 8]);    \
        } else {                                                                 \
            int bseg = seg - 1024;                                               \
            int row = bseg >> 3, sgi = bseg & 7;                                 \
            uint32_t off = (uint32_t)(row * 128 + sgi * 16);                     \
            cp_async16(base + A_BYTES + SWZ(off),                                \
                       &g_bpack[(size_t)(cb + row) * KPACK + kc0 + sgi * 8]);    \
        }                                                                        \
    }                                                                            \
} while (0)

    LOAD_CHUNK(0, 0);
    CP_COMMIT();

#pragma unroll 1
    for (int c = 0; c < 2; c++) {
        int buf = c & 1;
        if (c < 1) {
            LOAD_CHUNK(c + 1, buf ^ 1);
            CP_COMMIT();
            CP_WAIT(1);
        } else {
            CP_WAIT(0);
        }
        __syncthreads();

        uint32_t abase = sbase + buf * BUF_BYTES;
        uint32_t bbase = abase + A_BYTES;
#pragma unroll
        for (int ks = 0; ks < 4; ks++) {
            uint32_t a[4][4], b[2][4];
#pragma unroll
            for (int mt = 0; mt < 4; mt++) {
                int row = wm * 64 + mt * 16 + (lane & 15);
                uint32_t off = (uint32_t)(row * 128 + ks * 32 + ((lane >> 4) & 1) * 16);
                ldsm_x4(a[mt][0], a[mt][1], a[mt][2], a[mt][3], abase + SWZ(off));
            }
#pragma unroll
            for (int nt = 0; nt < 2; nt++) {
                int row = wn * 32 + nt * 16 + (lane & 15);
                uint32_t off = (uint32_t)(row * 128 + ks * 32 + ((lane >> 4) & 1) * 16);
                ldsm_x4(b[nt][0], b[nt][1], b[nt][2], b[nt][3], bbase + SWZ(off));
            }
#pragma unroll
            for (int mt = 0; mt < 4; mt++)
#pragma unroll
                for (int nt = 0; nt < 2; nt++) {
                    mma_f16(acc[mt][nt * 2][0], acc[mt][nt * 2][1],
                            acc[mt][nt * 2][2], acc[mt][nt * 2][3],
                            a[mt][0], a[mt][1], a[mt][2], a[mt][3],
                            b[nt][0], b[nt][2]);
                    mma_f16(acc[mt][nt * 2 + 1][0], acc[mt][nt * 2 + 1][1],
                            acc[mt][nt * 2 + 1][2], acc[mt][nt * 2 + 1][3],
                            a[mt][0], a[mt][1], a[mt][2], a[mt][3],
                            b[nt][1], b[nt][3]);
                }
        }
        __syncthreads();
    }

#pragma unroll
    for (int mt = 0; mt < 4; mt++) {
#pragma unroll
        for (int nf = 0; nf < 4; nf++) {
            int row = rb + wm * 64 + mt * 16 + (lane >> 2);
            int col = cb + wn * 32 + nf * 8 + (lane & 3) * 2;
            *(float2*)&adj[(size_t)row * 8192 + col] =
                make_float2(acc[mt][nf][0], acc[mt][nf][1]);
            *(float2*)&adj[(size_t)(row + 8) * 8192 + col] =
                make_float2(acc[mt][nf][2], acc[mt][nf][3]);
        }
    }
}

// ---------------- launch: two-arm schedule (round-12 structure) ----------------
extern "C" void kernel_launch(void* const* d_in, const int* in_sizes, int n_in,
                              void* d_out, int out_size) {
    (void)in_sizes; (void)n_in;
    const float* x  = (const float*)d_in[0];
    const void*  ei = d_in[1];
    const float *Ws = (const float*)d_in[2],  *bs  = (const float*)d_in[3];
    const float *Wt = (const float*)d_in[4],  *bt  = (const float*)d_in[5];
    const float *W1 = (const float*)d_in[6],  *b1  = (const float*)d_in[7];
    const float *W2 = (const float*)d_in[8],  *b2  = (const float*)d_in[9];
    const float *Wmu= (const float*)d_in[10], *bmu = (const float*)d_in[11];
    const float *W5 = (const float*)d_in[12], *b5  = (const float*)d_in[13];
    const float *W6 = (const float*)d_in[14], *b6  = (const float*)d_in[15];

    float* adj  = (float*)d_out;
    float* hout = (float*)d_out + ((size_t)out_size - (size_t)N_NODES * C_CH);

    cudaFuncSetAttribute(k_decoder, cudaFuncAttributeMaxDynamicSharedMemorySize,
                         DEC_SMEM);

    cudaStream_t sB;
    cudaStreamCreateWithFlags(&sB, cudaStreamNonBlocking);
    cudaEvent_t evStart, evPre, evX, evB;
    cudaEventCreateWithFlags(&evStart, cudaEventDisableTiming);
    cudaEventCreateWithFlags(&evPre,   cudaEventDisableTiming);
    cudaEventCreateWithFlags(&evX,     cudaEventDisableTiming);
    cudaEventCreateWithFlags(&evB,     cudaEventDisableTiming);

    // ---- fork ----
    cudaEventRecord(evStart, 0);
    cudaStreamWaitEvent(sB, evStart, 0);

    // ---- side stream: preprocessing (needs only ei) ----
    k_pre1<<<33, 256, 0, sB>>>((const int*)ei);
    k_deg<<<N_EDGES / 256, 256, 0, sB>>>(ei);
    k_scan_dis<<<1, 1024, 0, sB>>>();
    k_fill<<<N_EDGES / 256, 256, 0, sB>>>(ei);
    cudaEventRecord(evPre, sB);

    // ---- main stream: x @ {Ws, Wt, W1} (needs only x), overlapped with preproc ----
    k_gemm_x3<<<dim3(128, 3), 256>>>(x, Ws, Wt, W1);
    cudaEventRecord(evX, 0);

    // ---- side stream: NodeModel chain ----
    cudaStreamWaitEvent(sB, evX, 0);
    k_agg<<<1024, 256, 0, sB>>>(b1,  nullptr, 3, 1, 0);
    k_gemm_small<<<128, 256, 0, sB>>>(3, W2, 0);
    k_agg<<<1024, 256, 0, sB>>>(b2,  nullptr, 4, 1, 0);
    k_gemm_small<<<128, 256, 0, sB>>>(4, Wmu, 0);
    k_agg<<<1024, 256, 0, sB>>>(bmu, nullptr, 3, 0, 0);
    k_gemm_small<<<128, 256, 0, sB>>>(3, W5, 0);
    k_agg<<<1024, 256, 0, sB>>>(b5,  nullptr, 4, 1, 0);
    k_gemm_small<<<128, 256, 0, sB>>>(4, W6, 0);
    k_agg<<<1024, 256, 0, sB>>>(b6,  hout,    0, 1, 0);
    cudaEventRecord(evB, sB);

    // ---- main stream: s/t agg + packs (needs preproc + gemm_x3), then decoder ----
    cudaStreamWaitEvent(0, evPre, 0);
    k_agg_st<<<2048, 256>>>(bs, bt);
    k_decoder<<<dim3(64, 64), 256, DEC_SMEM>>>(adj);

    // ---- join ----
    cudaStreamWaitEvent(0, evB, 0);
}

// round 16
// speedup vs baseline: 1.1984x; 1.0482x over previous
#include <cuda_runtime.h>
#include <cuda_fp16.h>
#include <cstdint>

#define N_NODES 8192
#define C_CH    128
#define N_EDGES 262144
#define KPACK   128            // single fp16 product: K = C

// ---------------- scratch (device globals; no allocation allowed) ----------------
__device__ __align__(16) float g_dis[N_NODES];
__device__ __align__(16) int   g_cnt[N_NODES];
__device__ __align__(16) int   g_off[N_NODES];
__device__ __align__(16) int   g_cur[N_NODES];
__device__ __align__(16) int2  g_csr[N_EDGES];
__device__ __align__(16) float g_u1 [N_NODES * C_CH];   // NodeModel agg outputs (fp32)
__device__ __align__(16) float g_u2 [N_NODES * C_CH];
// fp16 gather mirrors (halve agg L2 traffic)
__device__ __align__(16) __half g_h16[N_NODES * C_CH];
__device__ __align__(16) __half g_s16[N_NODES * C_CH];
__device__ __align__(16) __half g_t16[N_NODES * C_CH];
// packed fp16 decoder operands: A=Sh, B=Th
__device__ __align__(16) __half g_apack[N_NODES * KPACK];
__device__ __align__(16) __half g_bpack[N_NODES * KPACK];
__device__ int g_is64;

__device__ __forceinline__ float* buf_ptr(int s) {
    switch (s) {
        case 4: return g_u2;
        default: return g_u1;
    }
}

// ---------------- preproc 1: edge dtype detect (block 0) + zero counts ----------------
__global__ void k_pre1(const int* __restrict__ v) {
    if (blockIdx.x == 0) {
        __shared__ int any;
        if (threadIdx.x == 0) any = 0;
        __syncthreads();
        int acc = 0;
        for (int i = threadIdx.x; i < 8192; i += 256) {
            int idx = i * 64 + 1;            // odd word, < 2*E
            acc |= v[idx];
        }
        if (acc) atomicOr(&any, 1);
        __syncthreads();
        if (threadIdx.x == 0) g_is64 = (any == 0) ? 1 : 0;
    } else {
        int i = (blockIdx.x - 1) * 256 + threadIdx.x;
        g_cnt[i] = 0;
    }
}

__device__ __forceinline__ int edge_at(const void* ei, int idx) {
    int v;
    if (g_is64) v = (int)((const long long*)ei)[idx];
    else        v = ((const int*)ei)[idx];
    return v & (N_NODES - 1);
}

__global__ void k_deg(const void* __restrict__ ei) {
    int e = blockIdx.x * blockDim.x + threadIdx.x;
    if (e < N_EDGES) atomicAdd(&g_cnt[edge_at(ei, N_EDGES + e)], 1);
}

// scan (1 block) + dis computation fused
__global__ void k_scan_dis() {
    __shared__ int part[1024];
    int t = threadIdx.x;
    int base = t * 8;
    int loc[8];
    int s = 0;
#pragma unroll
    for (int i = 0; i < 8; i++) {
        loc[i] = g_cnt[base + i];
        g_dis[base + i] = rsqrtf((float)loc[i] + 1.0f);
        s += loc[i];
    }
    part[t] = s;
    __syncthreads();
    for (int off = 1; off < 1024; off <<= 1) {
        int v = 0;
        if (t >= off) v = part[t - off];
        __syncthreads();
        part[t] += v;
        __syncthreads();
    }
    int run = part[t] - s;
#pragma unroll
    for (int i = 0; i < 8; i++) {
        g_off[base + i] = run;
        g_cur[base + i] = run;
        run += loc[i];
    }
}

__global__ void k_fill(const void* __restrict__ ei) {
    int e = blockIdx.x * blockDim.x + threadIdx.x;
    if (e < N_EDGES) {
        int s = edge_at(ei, e);
        int d = edge_at(ei, N_EDGES + e);
        float w = g_dis[s] * g_dis[d];
        int p = atomicAdd(&g_cur[d], 1);
        if (p < N_EDGES) g_csr[p] = make_int2(s, __float_as_int(w));
    }
}

// ---------------- fp16-gather agg: one warp per node, mirror input ----------------
__device__ __forceinline__ float4 agg_node16(const uint2* __restrict__ H2,
                                             int node, int lane,
                                             float4 bb, int relu) {
    float  di = g_dis[node];
    float  dd = di * di;
    uint2  hv = H2[(size_t)node * 32 + lane];
    float2 f01 = __half22float2(*(__half2*)&hv.x);
    float2 f23 = __half22float2(*(__half2*)&hv.y);
    float4 acc;
    acc.x = fmaf(f01.x, dd, bb.x);
    acc.y = fmaf(f01.y, dd, bb.y);
    acc.z = fmaf(f23.x, dd, bb.z);
    acc.w = fmaf(f23.y, dd, bb.w);
    float4 acc2 = make_float4(0.f, 0.f, 0.f, 0.f);

    int start = g_off[node];
    int cnt   = g_cnt[node];
    int j = 0;
    for (; j + 1 < cnt; j += 2) {
        int2 e0 = g_csr[start + j];
        int2 e1 = g_csr[start + j + 1];
        float w0 = __int_as_float(e0.y);
        float w1 = __int_as_float(e1.y);
        uint2 v0 = H2[(size_t)e0.x * 32 + lane];
        uint2 v1 = H2[(size_t)e1.x * 32 + lane];
        float2 a01 = __half22float2(*(__half2*)&v0.x);
        float2 a23 = __half22float2(*(__half2*)&v0.y);
        float2 b01 = __half22float2(*(__half2*)&v1.x);
        float2 b23 = __half22float2(*(__half2*)&v1.y);
        acc.x  = fmaf(a01.x, w0, acc.x);  acc.y  = fmaf(a01.y, w0, acc.y);
        acc.z  = fmaf(a23.x, w0, acc.z);  acc.w  = fmaf(a23.y, w0, acc.w);
        acc2.x = fmaf(b01.x, w1, acc2.x); acc2.y = fmaf(b01.y, w1, acc2.y);
        acc2.z = fmaf(b23.x, w1, acc2.z); acc2.w = fmaf(b23.y, w1, acc2.w);
    }
    if (j < cnt) {
        int2 e0 = g_csr[start + j];
        float w0 = __int_as_float(e0.y);
        uint2 v0 = H2[(size_t)e0.x * 32 + lane];
        float2 a01 = __half22float2(*(__half2*)&v0.x);
        float2 a23 = __half22float2(*(__half2*)&v0.y);
        acc.x = fmaf(a01.x, w0, acc.x); acc.y = fmaf(a01.y, w0, acc.y);
        acc.z = fmaf(a23.x, w0, acc.z); acc.w = fmaf(a23.y, w0, acc.w);
    }
    acc.x += acc2.x; acc.y += acc2.y; acc.z += acc2.z; acc.w += acc2.w;
    if (relu) {
        acc.x = fmaxf(acc.x, 0.f); acc.y = fmaxf(acc.y, 0.f);
        acc.z = fmaxf(acc.z, 0.f); acc.w = fmaxf(acc.w, 0.f);
    }
    return acc;
}

// ---------------- epilogue helper: 8 fp32 -> 8 fp16 (one uint4 store) ----------------
__device__ __forceinline__ void store_h16(__half* dst, const float* v) {
    __half tmp[8];
#pragma unroll
    for (int i = 0; i < 8; i++) tmp[i] = __float2half_rn(v[i]);
    *(uint4*)dst = *(uint4*)tmp;
}

// ---------------- dense GEMM (NodeModel): g_h16 = buf_ptr(selA) @ W ----------------
__global__ __launch_bounds__(256) void k_gemm_small(int selA,
                                                    const float* __restrict__ W) {
    __shared__ float Wsm[32 * 128];
    __shared__ float Asm[64 * 40];

    const float* A = buf_ptr(selA);
    int tid = threadIdx.x;
    int rb  = blockIdx.x * 64;
    int cg = tid & 15, rg = tid >> 4;
    int r0 = rg * 4, c0 = cg * 8;

    float acc[4][8];
#pragma unroll
    for (int i = 0; i < 4; i++)
#pragma unroll
        for (int j = 0; j < 8; j++) acc[i][j] = 0.f;

    for (int c = 0; c < 4; c++) {
        int kc0 = c * 32;
        __syncthreads();
#pragma unroll
        for (int i = 0; i < 4; i++) {
            int idx = tid + i * 256;
            int k = idx >> 5, c4 = idx & 31;
            *(float4*)&Wsm[k * 128 + c4 * 4] =
                *(const float4*)&W[(size_t)(kc0 + k) * 128 + c4 * 4];
        }
#pragma unroll
        for (int i = 0; i < 2; i++) {
            int idx = tid + i * 256;
            int row = idx >> 3, c4 = idx & 7;
            *(float4*)&Asm[row * 40 + c4 * 4] =
                *(const float4*)&A[(size_t)(rb + row) * 128 + kc0 + c4 * 4];
        }
        __syncthreads();

#pragma unroll
        for (int k = 0; k < 32; k += 4) {
            float4 a[4];
#pragma unroll
            for (int i = 0; i < 4; i++) a[i] = *(const float4*)&Asm[(r0 + i) * 40 + k];
#pragma unroll
            for (int kk = 0; kk < 4; kk++) {
                float4 bLo = *(const float4*)&Wsm[(k + kk) * 128 + c0];
                float4 bHi = *(const float4*)&Wsm[(k + kk) * 128 + c0 + 4];
                float bv[8] = {bLo.x, bLo.y, bLo.z, bLo.w, bHi.x, bHi.y, bHi.z, bHi.w};
#pragma unroll
                for (int i = 0; i < 4; i++) {
                    float av = (kk == 0) ? a[i].x : (kk == 1) ? a[i].y
                               : (kk == 2) ? a[i].z : a[i].w;
#pragma unroll
                    for (int j = 0; j < 8; j++)
                        acc[i][j] = fmaf(av, bv[j], acc[i][j]);
                }
            }
        }
    }

#pragma unroll
    for (int i = 0; i < 4; i++) {
        size_t base = (size_t)(rb + r0 + i) * 128 + c0;
        store_h16(&g_h16[base], acc[i]);
    }
}

// ---------------- k_gemm_x3: x @ {Ws, Wt, W1} -> fp16 mirrors only ----------------
__global__ __launch_bounds__(256) void k_gemm_x3(const float* __restrict__ x,
                                                 const float* __restrict__ Ws,
                                                 const float* __restrict__ Wt,
                                                 const float* __restrict__ W1) {
    __shared__ float Wsm[32 * 128];
    __shared__ float Asm[64 * 40];

    const float* W;
    __half* M16;
    if (blockIdx.y == 0)      { W = Ws; M16 = g_s16; }
    else if (blockIdx.y == 1) { W = Wt; M16 = g_t16; }
    else                      { W = W1; M16 = g_h16; }

    int tid = threadIdx.x;
    int rb  = blockIdx.x * 64;
    int cg = tid & 15, rg = tid >> 4;
    int r0 = rg * 4, c0 = cg * 8;

    float acc[4][8];
#pragma unroll
    for (int i = 0; i < 4; i++)
#pragma unroll
        for (int j = 0; j < 8; j++) acc[i][j] = 0.f;

    for (int c = 0; c < 4; c++) {
        int kc0 = c * 32;
        __syncthreads();
#pragma unroll
        for (int i = 0; i < 4; i++) {
            int idx = tid + i * 256;
            int k = idx >> 5, c4 = idx & 31;
            *(float4*)&Wsm[k * 128 + c4 * 4] =
                *(const float4*)&W[(size_t)(kc0 + k) * 128 + c4 * 4];
        }
#pragma unroll
        for (int i = 0; i < 2; i++) {
            int idx = tid + i * 256;
            int row = idx >> 3, c4 = idx & 7;
            *(float4*)&Asm[row * 40 + c4 * 4] =
                *(const float4*)&x[(size_t)(rb + row) * 128 + kc0 + c4 * 4];
        }
        __syncthreads();

#pragma unroll
        for (int k = 0; k < 32; k += 4) {
            float4 a[4];
#pragma unroll
            for (int i = 0; i < 4; i++) a[i] = *(const float4*)&Asm[(r0 + i) * 40 + k];
#pragma unroll
            for (int kk = 0; kk < 4; kk++) {
                float4 bLo = *(const float4*)&Wsm[(k + kk) * 128 + c0];
                float4 bHi = *(const float4*)&Wsm[(k + kk) * 128 + c0 + 4];
                float bv[8] = {bLo.x, bLo.y, bLo.z, bLo.w, bHi.x, bHi.y, bHi.z, bHi.w};
#pragma unroll
                for (int i = 0; i < 4; i++) {
                    float av = (kk == 0) ? a[i].x : (kk == 1) ? a[i].y
                               : (kk == 2) ? a[i].z : a[i].w;
#pragma unroll
                    for (int j = 0; j < 8; j++)
                        acc[i][j] = fmaf(av, bv[j], acc[i][j]);
                }
            }
        }
    }

#pragma unroll
    for (int i = 0; i < 4; i++) {
        size_t base = (size_t)(rb + r0 + i) * 128 + c0;
        store_h16(&M16[base], acc[i]);
    }
}

// ---------------- GCN aggregation (1024 blocks): fp16 gather from g_h16 ----------------
__global__ __launch_bounds__(256) void k_agg(const float* __restrict__ bias,
                                             float* __restrict__ Oext, int selO,
                                             int relu) {
    float* O = Oext ? Oext : buf_ptr(selO);
    const uint2* H2 = (const uint2*)g_h16;
    int warp = threadIdx.x >> 5, lane = threadIdx.x & 31;
    int node = blockIdx.x * 8 + warp;
    float4 bb = ((const float4*)bias)[lane];
    float4 acc = agg_node16(H2, node, lane, bb, relu);
    ((float4*)O)[(size_t)node * 32 + lane] = acc;
}

// ---------------- k_agg_st (2048 blocks): fp16 gather, write decoder packs ----------------
__global__ __launch_bounds__(256) void k_agg_st(const float* __restrict__ bs,
                                                const float* __restrict__ bt) {
    int warp = threadIdx.x >> 5, lane = threadIdx.x & 31;
    int smode = (blockIdx.x < 1024);
    int node = (smode ? blockIdx.x : blockIdx.x - 1024) * 8 + warp;
    const uint2* H2 = (const uint2*)(smode ? g_s16 : g_t16);
    const float* bias = smode ? bs : bt;

    float4 bb = ((const float4*)bias)[lane];
    float4 acc = agg_node16(H2, node, lane, bb, 0);

    __half p0 = __float2half_rn(acc.x), p1 = __float2half_rn(acc.y);
    __half p2 = __float2half_rn(acc.z), p3 = __float2half_rn(acc.w);
    __half pk[4] = {p0, p1, p2, p3};
    size_t pb = (size_t)node * KPACK + lane * 4;
    if (smode) *(uint2*)&g_apack[pb] = *(uint2*)pk;
    else       *(uint2*)&g_bpack[pb] = *(uint2*)pk;
}

// ---------------- HMMA decoder: adj = Apack @ Bpack^T (fp16, K=128) ----------------
// Block 128x128, 8 warps (2m x 4n), warp tile m64 x n32, 2 CTAs/SM
__device__ __forceinline__ void ldsm_x4(uint32_t& r0, uint32_t& r1,
                                        uint32_t& r2, uint32_t& r3, uint32_t a) {
    asm volatile("ldmatrix.sync.aligned.m8n8.x4.shared.b16 {%0,%1,%2,%3}, [%4];"
                 : "=r"(r0), "=r"(r1), "=r"(r2), "=r"(r3) : "r"(a));
}
__device__ __forceinline__ void mma_f16(float& c0, float& c1, float& c2, float& c3,
                                        uint32_t a0, uint32_t a1, uint32_t a2, uint32_t a3,
                                        uint32_t b0, uint32_t b1) {
    asm volatile(
        "mma.sync.aligned.m16n8k16.row.col.f32.f16.f16.f32 "
        "{%0,%1,%2,%3}, {%4,%5,%6,%7}, {%8,%9}, {%0,%1,%2,%3};"
        : "+f"(c0), "+f"(c1), "+f"(c2), "+f"(c3)
        : "r"(a0), "r"(a1), "r"(a2), "r"(a3), "r"(b0), "r"(b1));
}
__device__ __forceinline__ void cp_async16(uint32_t dst, const void* src) {
    asm volatile("cp.async.cg.shared.global [%0], [%1], 16;" :: "r"(dst), "l"(src));
}
#define CP_COMMIT() asm volatile("cp.async.commit_group;" ::: "memory")
#define CP_WAIT(n)  asm volatile("cp.async.wait_group %0;" :: "n"(n) : "memory")
#define SWZ(off) ((off) ^ (((off) >> 3) & 0x70))

#define A_BYTES   16384        // 128 rows x 128B (Kc=64)
#define B_BYTES   16384        // 128 rows x 128B
#define BUF_BYTES (A_BYTES + B_BYTES)   // 32 KB
#define DEC_SMEM  (2 * BUF_BYTES)       // 64 KB

__global__ __launch_bounds__(256, 2) void k_decoder(float* __restrict__ adj) {
    extern __shared__ __align__(16) char smem[];
    uint32_t sbase = (uint32_t)__cvta_generic_to_shared(smem);

    int tid  = threadIdx.x;
    int wid  = tid >> 5, lane = tid & 31;
    int wm   = wid >> 2, wn = wid & 3;        // 2 x 4 warp grid, warp tile m64 n32
    int cb   = blockIdx.x * 128;              // N offset
    int rb   = blockIdx.y * 128;              // M offset

    float acc[4][4][4];                       // 4 m16-frags x 4 n8-frags x 4
#pragma unroll
    for (int m = 0; m < 4; m++)
#pragma unroll
        for (int n = 0; n < 4; n++)
#pragma unroll
            for (int r = 0; r < 4; r++) acc[m][n][r] = 0.f;

#define LOAD_CHUNK(c, buf) do {                                                  \
    int kc0 = (c) * 64;                                                          \
    uint32_t base = sbase + (buf) * BUF_BYTES;                                   \
    _Pragma("unroll")                                                            \
    for (int i = 0; i < 8; i++) {                                                \
        int seg = tid + i * 256;                                                 \
        if (seg < 1024) {                                                        \
            int row = seg >> 3, sgi = seg & 7;                                   \
            uint32_t off = (uint32_t)(row * 128 + sgi * 16);                     \
            cp_async16(base + SWZ(off),                                          \
                       &g_apack[(size_t)(rb + row) * KPACK + kc0 + sgi * 8]);    \
        } else {                                                                 \
            int bseg = seg - 1024;                                               \
            int row = bseg >> 3, sgi = bseg & 7;                                 \
            uint32_t off = (uint32_t)(row * 128 + sgi * 16);                     \
            cp_async16(base + A_BYTES + SWZ(off),                                \
                       &g_bpack[(size_t)(cb + row) * KPACK + kc0 + sgi * 8]);    \
        }                                                                        \
    }                                                                            \
} while (0)

    LOAD_CHUNK(0, 0);
    CP_COMMIT();

#pragma unroll 1
    for (int c = 0; c < 2; c++) {
        int buf = c & 1;
        if (c < 1) {
            LOAD_CHUNK(c + 1, buf ^ 1);
            CP_COMMIT();
            CP_WAIT(1);
        } else {
            CP_WAIT(0);
        }
        __syncthreads();

        uint32_t abase = sbase + buf * BUF_BYTES;
        uint32_t bbase = abase + A_BYTES;
#pragma unroll
        for (int ks = 0; ks < 4; ks++) {
            uint32_t a[4][4], b[2][4];
#pragma unroll
            for (int mt = 0; mt < 4; mt++) {
                int row = wm * 64 + mt * 16 + (lane & 15);
                uint32_t off = (uint32_t)(row * 128 + ks * 32 + ((lane >> 4) & 1) * 16);
                ldsm_x4(a[mt][0], a[mt][1], a[mt][2], a[mt][3], abase + SWZ(off));
            }
#pragma unroll
            for (int nt = 0; nt < 2; nt++) {
                int row = wn * 32 + nt * 16 + (lane & 15);
                uint32_t off = (uint32_t)(row * 128 + ks * 32 + ((lane >> 4) & 1) * 16);
                ldsm_x4(b[nt][0], b[nt][1], b[nt][2], b[nt][3], bbase + SWZ(off));
            }
#pragma unroll
            for (int mt = 0; mt < 4; mt++)
#pragma unroll
                for (int nt = 0; nt < 2; nt++) {
                    mma_f16(acc[mt][nt * 2][0], acc[mt][nt * 2][1],
                            acc[mt][nt * 2][2], acc[mt][nt * 2][3],
                            a[mt][0], a[mt][1], a[mt][2], a[mt][3],
                            b[nt][0], b[nt][2]);
                    mma_f16(acc[mt][nt * 2 + 1][0], acc[mt][nt * 2 + 1][1],
                            acc[mt][nt * 2 + 1][2], acc[mt][nt * 2 + 1][3],
                            a[mt][0], a[mt][1], a[mt][2], a[mt][3],
                            b[nt][1], b[nt][3]);
                }
        }
        __syncthreads();
    }

#pragma unroll
    for (int mt = 0; mt < 4; mt++) {
#pragma unroll
        for (int nf = 0; nf < 4; nf++) {
            int row = rb + wm * 64 + mt * 16 + (lane >> 2);
            int col = cb + wn * 32 + nf * 8 + (lane & 3) * 2;
            *(float2*)&adj[(size_t)row * 8192 + col] =
                make_float2(acc[mt][nf][0], acc[mt][nf][1]);
            *(float2*)&adj[(size_t)(row + 8) * 8192 + col] =
                make_float2(acc[mt][nf][2], acc[mt][nf][3]);
        }
    }
}

// ---------------- launch: two-arm schedule, fp16 gather everywhere ----------------
extern "C" void kernel_launch(void* const* d_in, const int* in_sizes, int n_in,
                              void* d_out, int out_size) {
    (void)in_sizes; (void)n_in;
    const float* x  = (const float*)d_in[0];
    const void*  ei = d_in[1];
    const float *Ws = (const float*)d_in[2],  *bs  = (const float*)d_in[3];
    const float *Wt = (const float*)d_in[4],  *bt  = (const float*)d_in[5];
    const float *W1 = (const float*)d_in[6],  *b1  = (const float*)d_in[7];
    const float *W2 = (const float*)d_in[8],  *b2  = (const float*)d_in[9];
    const float *Wmu= (const float*)d_in[10], *bmu = (const float*)d_in[11];
    const float *W5 = (const float*)d_in[12], *b5  = (const float*)d_in[13];
    const float *W6 = (const float*)d_in[14], *b6  = (const float*)d_in[15];

    float* adj  = (float*)d_out;
    float* hout = (float*)d_out + ((size_t)out_size - (size_t)N_NODES * C_CH);

    cudaFuncSetAttribute(k_decoder, cudaFuncAttributeMaxDynamicSharedMemorySize,
                         DEC_SMEM);

    cudaStream_t sB;
    cudaStreamCreateWithFlags(&sB, cudaStreamNonBlocking);
    cudaEvent_t evStart, evPre, evX, evB;
    cudaEventCreateWithFlags(&evStart, cudaEventDisableTiming);
    cudaEventCreateWithFlags(&evPre,   cudaEventDisableTiming);
    cudaEventCreateWithFlags(&evX,     cudaEventDisableTiming);
    cudaEventCreateWithFlags(&evB,     cudaEventDisableTiming);

    // ---- fork ----
    cudaEventRecord(evStart, 0);
    cudaStreamWaitEvent(sB, evStart, 0);

    // ---- side stream: preprocessing (needs only ei) ----
    k_pre1<<<33, 256, 0, sB>>>((const int*)ei);
    k_deg<<<N_EDGES / 256, 256, 0, sB>>>(ei);
    k_scan_dis<<<1, 1024, 0, sB>>>();
    k_fill<<<N_EDGES / 256, 256, 0, sB>>>(ei);
    cudaEventRecord(evPre, sB);

    // ---- main stream: x @ {Ws, Wt, W1} (needs only x), overlapped with preproc ----
    k_gemm_x3<<<dim3(128, 3), 256>>>(x, Ws, Wt, W1);
    cudaEventRecord(evX, 0);

    // ---- side stream: NodeModel chain (fp16 gather) ----
    cudaStreamWaitEvent(sB, evX, 0);
    k_agg<<<1024, 256, 0, sB>>>(b1,  nullptr, 3, 1);      // g_h16 -> u1
    k_gemm_small<<<128, 256, 0, sB>>>(3, W2);             // u1 -> g_h16
    k_agg<<<1024, 256, 0, sB>>>(b2,  nullptr, 4, 1);      // -> u2
    k_gemm_small<<<128, 256, 0, sB>>>(4, Wmu);
    k_agg<<<1024, 256, 0, sB>>>(bmu, nullptr, 3, 0);      // -> u1 (no relu)
    k_gemm_small<<<128, 256, 0, sB>>>(3, W5);
    k_agg<<<1024, 256, 0, sB>>>(b5,  nullptr, 4, 1);      // -> u2
    k_gemm_small<<<128, 256, 0, sB>>>(4, W6);
    k_agg<<<1024, 256, 0, sB>>>(b6,  hout,    0, 1);      // -> hout
    cudaEventRecord(evB, sB);

    // ---- main stream: s/t agg + packs (needs preproc + gemm_x3), then decoder ----
    cudaStreamWaitEvent(0, evPre, 0);
    k_agg_st<<<2048, 256>>>(bs, bt);
    k_decoder<<<dim3(64, 64), 256, DEC_SMEM>>>(adj);

    // ---- join ----
    cudaStreamWaitEvent(0, evB, 0);
}

// round 17
// speedup vs baseline: 1.2005x; 1.0018x over previous
#include <cuda_runtime.h>
#include <cuda_fp16.h>
#include <cstdint>

#define N_NODES 8192
#define C_CH    128
#define N_EDGES 262144
#define KPACK   128            // single fp16 product: K = C

// ---------------- scratch (device globals; no allocation allowed) ----------------
__device__ __align__(16) float g_dis[N_NODES];
__device__ __align__(16) int   g_cnt[N_NODES];          // ALWAYS 0 at launch entry
__device__ __align__(16) int   g_off[N_NODES + 1];      // CSR offsets, off[N]=E
__device__ __align__(16) int   g_cur[N_NODES];
__device__ __align__(16) int2  g_csr[N_EDGES];
__device__ __align__(16) float g_u1 [N_NODES * C_CH];   // NodeModel agg outputs (fp32)
__device__ __align__(16) float g_u2 [N_NODES * C_CH];
// fp16 gather mirrors (halve agg L2 traffic)
__device__ __align__(16) __half g_h16[N_NODES * C_CH];
__device__ __align__(16) __half g_s16[N_NODES * C_CH];
__device__ __align__(16) __half g_t16[N_NODES * C_CH];
// packed fp16 decoder operands: A=Sh, B=Th
__device__ __align__(16) __half g_apack[N_NODES * KPACK];
__device__ __align__(16) __half g_bpack[N_NODES * KPACK];
__device__ int g_is64;

__device__ __forceinline__ float* buf_ptr(int s) {
    switch (s) {
        case 4: return g_u2;
        default: return g_u1;
    }
}

// ---------------- edge dtype detect (1 block) ----------------
__global__ void k_detect(const int* __restrict__ v) {
    __shared__ int any;
    if (threadIdx.x == 0) any = 0;
    __syncthreads();
    int acc = 0;
    for (int i = threadIdx.x; i < 8192; i += 256) {
        int idx = i * 64 + 1;            // odd word, < 2*E
        acc |= v[idx];
    }
    if (acc) atomicOr(&any, 1);
    __syncthreads();
    if (threadIdx.x == 0) g_is64 = (any == 0) ? 1 : 0;
}

__device__ __forceinline__ int edge_at(const void* ei, int idx) {
    int v;
    if (g_is64) v = (int)((const long long*)ei)[idx];
    else        v = ((const int*)ei)[idx];
    return v & (N_NODES - 1);
}

// ---------------- degree count: 4 independent edges per thread (MLP=4) ----------------
__global__ void k_deg(const void* __restrict__ ei) {
    int base = blockIdx.x * 256 + threadIdx.x;
#pragma unroll
    for (int i = 0; i < 4; i++) {
        int e = base + i * 65536;
        atomicAdd(&g_cnt[edge_at(ei, N_EDGES + e)], 1);
    }
}

// scan (1 block) + dis + self-zero of g_cnt (restores entry invariant) + off[N]=E
__global__ void k_scan_dis() {
    __shared__ int part[1024];
    int t = threadIdx.x;
    int base = t * 8;
    int loc[8];
    int s = 0;
#pragma unroll
    for (int i = 0; i < 8; i++) {
        loc[i] = g_cnt[base + i];
        g_cnt[base + i] = 0;                          // zero for next launch
        g_dis[base + i] = rsqrtf((float)loc[i] + 1.0f);
        s += loc[i];
    }
    part[t] = s;
    __syncthreads();
    for (int off = 1; off < 1024; off <<= 1) {
        int v = 0;
        if (t >= off) v = part[t - off];
        __syncthreads();
        part[t] += v;
        __syncthreads();
    }
    int run = part[t] - s;
#pragma unroll
    for (int i = 0; i < 8; i++) {
        g_off[base + i] = run;
        g_cur[base + i] = run;
        run += loc[i];
    }
    if (t == 1023) g_off[N_NODES] = run;              // = N_EDGES
}

// CSR fill: 4 independent edges per thread
__global__ void k_fill(const void* __restrict__ ei) {
    int base = blockIdx.x * 256 + threadIdx.x;
#pragma unroll
    for (int i = 0; i < 4; i++) {
        int e = base + i * 65536;
        int s = edge_at(ei, e);
        int d = edge_at(ei, N_EDGES + e);
        float w = g_dis[s] * g_dis[d];
        int p = atomicAdd(&g_cur[d], 1);
        if (p < N_EDGES) g_csr[p] = make_int2(s, __float_as_int(w));
    }
}

// ---------------- fp16-gather agg: one warp per node, cnt from off-delta ----------------
__device__ __forceinline__ float4 agg_node16(const uint2* __restrict__ H2,
                                             int node, int lane,
                                             float4 bb, int relu) {
    float  di = g_dis[node];
    float  dd = di * di;
    uint2  hv = H2[(size_t)node * 32 + lane];
    float2 f01 = __half22float2(*(__half2*)&hv.x);
    float2 f23 = __half22float2(*(__half2*)&hv.y);
    float4 acc;
    acc.x = fmaf(f01.x, dd, bb.x);
    acc.y = fmaf(f01.y, dd, bb.y);
    acc.z = fmaf(f23.x, dd, bb.z);
    acc.w = fmaf(f23.y, dd, bb.w);
    float4 acc2 = make_float4(0.f, 0.f, 0.f, 0.f);

    int start = g_off[node];
    int cnt   = g_off[node + 1] - start;
    int j = 0;
    for (; j + 1 < cnt; j += 2) {
        int2 e0 = g_csr[start + j];
        int2 e1 = g_csr[start + j + 1];
        float w0 = __int_as_float(e0.y);
        float w1 = __int_as_float(e1.y);
        uint2 v0 = H2[(size_t)e0.x * 32 + lane];
        uint2 v1 = H2[(size_t)e1.x * 32 + lane];
        float2 a01 = __half22float2(*(__half2*)&v0.x);
        float2 a23 = __half22float2(*(__half2*)&v0.y);
        float2 b01 = __half22float2(*(__half2*)&v1.x);
        float2 b23 = __half22float2(*(__half2*)&v1.y);
        acc.x  = fmaf(a01.x, w0, acc.x);  acc.y  = fmaf(a01.y, w0, acc.y);
        acc.z  = fmaf(a23.x, w0, acc.z);  acc.w  = fmaf(a23.y, w0, acc.w);
        acc2.x = fmaf(b01.x, w1, acc2.x); acc2.y = fmaf(b01.y, w1, acc2.y);
        acc2.z = fmaf(b23.x, w1, acc2.z); acc2.w = fmaf(b23.y, w1, acc2.w);
    }
    if (j < cnt) {
        int2 e0 = g_csr[start + j];
        float w0 = __int_as_float(e0.y);
        uint2 v0 = H2[(size_t)e0.x * 32 + lane];
        float2 a01 = __half22float2(*(__half2*)&v0.x);
        float2 a23 = __half22float2(*(__half2*)&v0.y);
        acc.x = fmaf(a01.x, w0, acc.x); acc.y = fmaf(a01.y, w0, acc.y);
        acc.z = fmaf(a23.x, w0, acc.z); acc.w = fmaf(a23.y, w0, acc.w);
    }
    acc.x += acc2.x; acc.y += acc2.y; acc.z += acc2.z; acc.w += acc2.w;
    if (relu) {
        acc.x = fmaxf(acc.x, 0.f); acc.y = fmaxf(acc.y, 0.f);
        acc.z = fmaxf(acc.z, 0.f); acc.w = fmaxf(acc.w, 0.f);
    }
    return acc;
}

// ---------------- epilogue helper: 8 fp32 -> 8 fp16 (one uint4 store) ----------------
__device__ __forceinline__ void store_h16(__half* dst, const float* v) {
    __half tmp[8];
#pragma unroll
    for (int i = 0; i < 8; i++) tmp[i] = __float2half_rn(v[i]);
    *(uint4*)dst = *(uint4*)tmp;
}

// ---------------- dense GEMM (NodeModel): g_h16 = buf_ptr(selA) @ W ----------------
__global__ __launch_bounds__(256) void k_gemm_small(int selA,
                                                    const float* __restrict__ W) {
    __shared__ float Wsm[32 * 128];
    __shared__ float Asm[64 * 40];

    const float* A = buf_ptr(selA);
    int tid = threadIdx.x;
    int rb  = blockIdx.x * 64;
    int cg = tid & 15, rg = tid >> 4;
    int r0 = rg * 4, c0 = cg * 8;

    float acc[4][8];
#pragma unroll
    for (int i = 0; i < 4; i++)
#pragma unroll
        for (int j = 0; j < 8; j++) acc[i][j] = 0.f;

    for (int c = 0; c < 4; c++) {
        int kc0 = c * 32;
        __syncthreads();
#pragma unroll
        for (int i = 0; i < 4; i++) {
            int idx = tid + i * 256;
            int k = idx >> 5, c4 = idx & 31;
            *(float4*)&Wsm[k * 128 + c4 * 4] =
                *(const float4*)&W[(size_t)(kc0 + k) * 128 + c4 * 4];
        }
#pragma unroll
        for (int i = 0; i < 2; i++) {
            int idx = tid + i * 256;
            int row = idx >> 3, c4 = idx & 7;
            *(float4*)&Asm[row * 40 + c4 * 4] =
                *(const float4*)&A[(size_t)(rb + row) * 128 + kc0 + c4 * 4];
        }
        __syncthreads();

#pragma unroll
        for (int k = 0; k < 32; k += 4) {
            float4 a[4];
#pragma unroll
            for (int i = 0; i < 4; i++) a[i] = *(const float4*)&Asm[(r0 + i) * 40 + k];
#pragma unroll
            for (int kk = 0; kk < 4; kk++) {
                float4 bLo = *(const float4*)&Wsm[(k + kk) * 128 + c0];
                float4 bHi = *(const float4*)&Wsm[(k + kk) * 128 + c0 + 4];
                float bv[8] = {bLo.x, bLo.y, bLo.z, bLo.w, bHi.x, bHi.y, bHi.z, bHi.w};
#pragma unroll
                for (int i = 0; i < 4; i++) {
                    float av = (kk == 0) ? a[i].x : (kk == 1) ? a[i].y
                               : (kk == 2) ? a[i].z : a[i].w;
#pragma unroll
                    for (int j = 0; j < 8; j++)
                        acc[i][j] = fmaf(av, bv[j], acc[i][j]);
                }
            }
        }
    }

#pragma unroll
    for (int i = 0; i < 4; i++) {
        size_t base = (size_t)(rb + r0 + i) * 128 + c0;
        store_h16(&g_h16[base], acc[i]);
    }
}

// ---------------- k_gemm_x3: x @ {Ws, Wt, W1} -> fp16 mirrors only ----------------
__global__ __launch_bounds__(256) void k_gemm_x3(const float* __restrict__ x,
                                                 const float* __restrict__ Ws,
                                                 const float* __restrict__ Wt,
                                                 const float* __restrict__ W1) {
    __shared__ float Wsm[32 * 128];
    __shared__ float Asm[64 * 40];

    const float* W;
    __half* M16;
    if (blockIdx.y == 0)      { W = Ws; M16 = g_s16; }
    else if (blockIdx.y == 1) { W = Wt; M16 = g_t16; }
    else                      { W = W1; M16 = g_h16; }

    int tid = threadIdx.x;
    int rb  = blockIdx.x * 64;
    int cg = tid & 15, rg = tid >> 4;
    int r0 = rg * 4, c0 = cg * 8;

    float acc[4][8];
#pragma unroll
    for (int i = 0; i < 4; i++)
#pragma unroll
        for (int j = 0; j < 8; j++) acc[i][j] = 0.f;

    for (int c = 0; c < 4; c++) {
        int kc0 = c * 32;
        __syncthreads();
#pragma unroll
        for (int i = 0; i < 4; i++) {
            int idx = tid + i * 256;
            int k = idx >> 5, c4 = idx & 31;
            *(float4*)&Wsm[k * 128 + c4 * 4] =
                *(const float4*)&W[(size_t)(kc0 + k) * 128 + c4 * 4];
        }
#pragma unroll
        for (int i = 0; i < 2; i++) {
            int idx = tid + i * 256;
            int row = idx >> 3, c4 = idx & 7;
            *(float4*)&Asm[row * 40 + c4 * 4] =
                *(const float4*)&x[(size_t)(rb + row) * 128 + kc0 + c4 * 4];
        }
        __syncthreads();

#pragma unroll
        for (int k = 0; k < 32; k += 4) {
            float4 a[4];
#pragma unroll
            for (int i = 0; i < 4; i++) a[i] = *(const float4*)&Asm[(r0 + i) * 40 + k];
#pragma unroll
            for (int kk = 0; kk < 4; kk++) {
                float4 bLo = *(const float4*)&Wsm[(k + kk) * 128 + c0];
                float4 bHi = *(const float4*)&Wsm[(k + kk) * 128 + c0 + 4];
                float bv[8] = {bLo.x, bLo.y, bLo.z, bLo.w, bHi.x, bHi.y, bHi.z, bHi.w};
#pragma unroll
                for (int i = 0; i < 4; i++) {
                    float av = (kk == 0) ? a[i].x : (kk == 1) ? a[i].y
                               : (kk == 2) ? a[i].z : a[i].w;
#pragma unroll
                    for (int j = 0; j < 8; j++)
                        acc[i][j] = fmaf(av, bv[j], acc[i][j]);
                }
            }
        }
    }

#pragma unroll
    for (int i = 0; i < 4; i++) {
        size_t base = (size_t)(rb + r0 + i) * 128 + c0;
        store_h16(&M16[base], acc[i]);
    }
}

// ---------------- GCN aggregation (1024 blocks): fp16 gather from g_h16 ----------------
__global__ __launch_bounds__(256) void k_agg(const float* __restrict__ bias,
                                             float* __restrict__ Oext, int selO,
                                             int relu) {
    float* O = Oext ? Oext : buf_ptr(selO);
    const uint2* H2 = (const uint2*)g_h16;
    int warp = threadIdx.x >> 5, lane = threadIdx.x & 31;
    int node = blockIdx.x * 8 + warp;
    float4 bb = ((const float4*)bias)[lane];
    float4 acc = agg_node16(H2, node, lane, bb, relu);
    ((float4*)O)[(size_t)node * 32 + lane] = acc;
}

// ---------------- k_agg_st (2048 blocks): fp16 gather, write decoder packs ----------------
__global__ __launch_bounds__(256) void k_agg_st(const float* __restrict__ bs,
                                                const float* __restrict__ bt) {
    int warp = threadIdx.x >> 5, lane = threadIdx.x & 31;
    int smode = (blockIdx.x < 1024);
    int node = (smode ? blockIdx.x : blockIdx.x - 1024) * 8 + warp;
    const uint2* H2 = (const uint2*)(smode ? g_s16 : g_t16);
    const float* bias = smode ? bs : bt;

    float4 bb = ((const float4*)bias)[lane];
    float4 acc = agg_node16(H2, node, lane, bb, 0);

    __half p0 = __float2half_rn(acc.x), p1 = __float2half_rn(acc.y);
    __half p2 = __float2half_rn(acc.z), p3 = __float2half_rn(acc.w);
    __half pk[4] = {p0, p1, p2, p3};
    size_t pb = (size_t)node * KPACK + lane * 4;
    if (smode) *(uint2*)&g_apack[pb] = *(uint2*)pk;
    else       *(uint2*)&g_bpack[pb] = *(uint2*)pk;
}

// ---------------- HMMA decoder: adj = Apack @ Bpack^T (fp16, K=128) ----------------
// Block 128x128, 8 warps (2m x 4n), warp tile m64 x n32, 2 CTAs/SM
__device__ __forceinline__ void ldsm_x4(uint32_t& r0, uint32_t& r1,
                                        uint32_t& r2, uint32_t& r3, uint32_t a) {
    asm volatile("ldmatrix.sync.aligned.m8n8.x4.shared.b16 {%0,%1,%2,%3}, [%4];"
                 : "=r"(r0), "=r"(r1), "=r"(r2), "=r"(r3) : "r"(a));
}
__device__ __forceinline__ void mma_f16(float& c0, float& c1, float& c2, float& c3,
                                        uint32_t a0, uint32_t a1, uint32_t a2, uint32_t a3,
                                        uint32_t b0, uint32_t b1) {
    asm volatile(
        "mma.sync.aligned.m16n8k16.row.col.f32.f16.f16.f32 "
        "{%0,%1,%2,%3}, {%4,%5,%6,%7}, {%8,%9}, {%0,%1,%2,%3};"
        : "+f"(c0), "+f"(c1), "+f"(c2), "+f"(c3)
        : "r"(a0), "r"(a1), "r"(a2), "r"(a3), "r"(b0), "r"(b1));
}
__device__ __forceinline__ void cp_async16(uint32_t dst, const void* src) {
    asm volatile("cp.async.cg.shared.global [%0], [%1], 16;" :: "r"(dst), "l"(src));
}
#define CP_COMMIT() asm volatile("cp.async.commit_group;" ::: "memory")
#define CP_WAIT(n)  asm volatile("cp.async.wait_group %0;" :: "n"(n) : "memory")
#define SWZ(off) ((off) ^ (((off) >> 3) & 0x70))

#define A_BYTES   16384        // 128 rows x 128B (Kc=64)
#define B_BYTES   16384        // 128 rows x 128B
#define BUF_BYTES (A_BYTES + B_BYTES)   // 32 KB
#define DEC_SMEM  (2 * BUF_BYTES)       // 64 KB

__global__ __launch_bounds__(256, 2) void k_decoder(float* __restrict__ adj) {
    extern __shared__ __align__(16) char smem[];
    uint32_t sbase = (uint32_t)__cvta_generic_to_shared(smem);

    int tid  = threadIdx.x;
    int wid  = tid >> 5, lane = tid & 31;
    int wm   = wid >> 2, wn = wid & 3;        // 2 x 4 warp grid, warp tile m64 n32
    int cb   = blockIdx.x * 128;              // N offset
    int rb   = blockIdx.y * 128;              // M offset

    float acc[4][4][4];                       // 4 m16-frags x 4 n8-frags x 4
#pragma unroll
    for (int m = 0; m < 4; m++)
#pragma unroll
        for (int n = 0; n < 4; n++)
#pragma unroll
            for (int r = 0; r < 4; r++) acc[m][n][r] = 0.f;

#define LOAD_CHUNK(c, buf) do {                                                  \
    int kc0 = (c) * 64;                                                          \
    uint32_t base = sbase + (buf) * BUF_BYTES;                                   \
    _Pragma("unroll")                                                            \
    for (int i = 0; i < 8; i++) {                                                \
        int seg = tid + i * 256;                                                 \
        if (seg < 1024) {                                                        \
            int row = seg >> 3, sgi = seg & 7;                                   \
            uint32_t off = (uint32_t)(row * 128 + sgi * 16);                     \
            cp_async16(base + SWZ(off),                                          \
                       &g_apack[(size_t)(rb + row) * KPACK + kc0 + sgi * 8]);    \
        } else {                                                                 \
            int bseg = seg - 1024;                                               \
            int row = bseg >> 3, sgi = bseg & 7;                                 \
            uint32_t off = (uint32_t)(row * 128 + sgi * 16);                     \
            cp_async16(base + A_BYTES + SWZ(off),                                \
                       &g_bpack[(size_t)(cb + row) * KPACK + kc0 + sgi * 8]);    \
        }                                                                        \
    }                                                                            \
} while (0)

    LOAD_CHUNK(0, 0);
    CP_COMMIT();

#pragma unroll 1
    for (int c = 0; c < 2; c++) {
        int buf = c & 1;
        if (c < 1) {
            LOAD_CHUNK(c + 1, buf ^ 1);
            CP_COMMIT();
            CP_WAIT(1);
        } else {
            CP_WAIT(0);
        }
        __syncthreads();

        uint32_t abase = sbase + buf * BUF_BYTES;
        uint32_t bbase = abase + A_BYTES;
#pragma unroll
        for (int ks = 0; ks < 4; ks++) {
            uint32_t a[4][4], b[2][4];
#pragma unroll
            for (int mt = 0; mt < 4; mt++) {
                int row = wm * 64 + mt * 16 + (lane & 15);
                uint32_t off = (uint32_t)(row * 128 + ks * 32 + ((lane >> 4) & 1) * 16);
                ldsm_x4(a[mt][0], a[mt][1], a[mt][2], a[mt][3], abase + SWZ(off));
            }
#pragma unroll
            for (int nt = 0; nt < 2; nt++) {
                int row = wn * 32 + nt * 16 + (lane & 15);
                uint32_t off = (uint32_t)(row * 128 + ks * 32 + ((lane >> 4) & 1) * 16);
                ldsm_x4(b[nt][0], b[nt][1], b[nt][2], b[nt][3], bbase + SWZ(off));
            }
#pragma unroll
            for (int mt = 0; mt < 4; mt++)
#pragma unroll
                for (int nt = 0; nt < 2; nt++) {
                    mma_f16(acc[mt][nt * 2][0], acc[mt][nt * 2][1],
                            acc[mt][nt * 2][2], acc[mt][nt * 2][3],
                            a[mt][0], a[mt][1], a[mt][2], a[mt][3],
                            b[nt][0], b[nt][2]);
                    mma_f16(acc[mt][nt * 2 + 1][0], acc[mt][nt * 2 + 1][1],
                            acc[mt][nt * 2 + 1][2], acc[mt][nt * 2 + 1][3],
                            a[mt][0], a[mt][1], a[mt][2], a[mt][3],
                            b[nt][1], b[nt][3]);
                }
        }
        __syncthreads();
    }

#pragma unroll
    for (int mt = 0; mt < 4; mt++) {
#pragma unroll
        for (int nf = 0; nf < 4; nf++) {
            int row = rb + wm * 64 + mt * 16 + (lane >> 2);
            int col = cb + wn * 32 + nf * 8 + (lane & 3) * 2;
            *(float2*)&adj[(size_t)row * 8192 + col] =
                make_float2(acc[mt][nf][0], acc[mt][nf][1]);
            *(float2*)&adj[(size_t)(row + 8) * 8192 + col] =
                make_float2(acc[mt][nf][2], acc[mt][nf][3]);
        }
    }
}

// ---------------- launch: two-arm schedule ----------------
extern "C" void kernel_launch(void* const* d_in, const int* in_sizes, int n_in,
                              void* d_out, int out_size) {
    (void)in_sizes; (void)n_in;
    const float* x  = (const float*)d_in[0];
    const void*  ei = d_in[1];
    const float *Ws = (const float*)d_in[2],  *bs  = (const float*)d_in[3];
    const float *Wt = (const float*)d_in[4],  *bt  = (const float*)d_in[5];
    const float *W1 = (const float*)d_in[6],  *b1  = (const float*)d_in[7];
    const float *W2 = (const float*)d_in[8],  *b2  = (const float*)d_in[9];
    const float *Wmu= (const float*)d_in[10], *bmu = (const float*)d_in[11];
    const float *W5 = (const float*)d_in[12], *b5  = (const float*)d_in[13];
    const float *W6 = (const float*)d_in[14], *b6  = (const float*)d_in[15];

    float* adj  = (float*)d_out;
    float* hout = (float*)d_out + ((size_t)out_size - (size_t)N_NODES * C_CH);

    cudaFuncSetAttribute(k_decoder, cudaFuncAttributeMaxDynamicSharedMemorySize,
                         DEC_SMEM);

    cudaStream_t sB;
    cudaStreamCreateWithFlags(&sB, cudaStreamNonBlocking);
    cudaEvent_t evStart, evPre, evX, evB;
    cudaEventCreateWithFlags(&evStart, cudaEventDisableTiming);
    cudaEventCreateWithFlags(&evPre,   cudaEventDisableTiming);
    cudaEventCreateWithFlags(&evX,     cudaEventDisableTiming);
    cudaEventCreateWithFlags(&evB,     cudaEventDisableTiming);

    // ---- fork ----
    cudaEventRecord(evStart, 0);
    cudaStreamWaitEvent(sB, evStart, 0);

    // ---- side stream: preprocessing (needs only ei; g_cnt==0 invariant) ----
    k_detect<<<1, 256, 0, sB>>>((const int*)ei);
    k_deg<<<256, 256, 0, sB>>>(ei);
    k_scan_dis<<<1, 1024, 0, sB>>>();
    k_fill<<<256, 256, 0, sB>>>(ei);
    cudaEventRecord(evPre, sB);

    // ---- main stream: x @ {Ws, Wt, W1} (needs only x), overlapped with preproc ----
    k_gemm_x3<<<dim3(128, 3), 256>>>(x, Ws, Wt, W1);
    cudaEventRecord(evX, 0);

    // ---- side stream: NodeModel chain (fp16 gather) ----
    cudaStreamWaitEvent(sB, evX, 0);
    k_agg<<<1024, 256, 0, sB>>>(b1,  nullptr, 3, 1);      // g_h16 -> u1
    k_gemm_small<<<128, 256, 0, sB>>>(3, W2);             // u1 -> g_h16
    k_agg<<<1024, 256, 0, sB>>>(b2,  nullptr, 4, 1);      // -> u2
    k_gemm_small<<<128, 256, 0, sB>>>(4, Wmu);
    k_agg<<<1024, 256, 0, sB>>>(bmu, nullptr, 3, 0);      // -> u1 (no relu)
    k_gemm_small<<<128, 256, 0, sB>>>(3, W5);
    k_agg<<<1024, 256, 0, sB>>>(b5,  nullptr, 4, 1);      // -> u2
    k_gemm_small<<<128, 256, 0, sB>>>(4, W6);
    k_agg<<<1024, 256, 0, sB>>>(b6,  hout,    0, 1);      // -> hout
    cudaEventRecord(evB, sB);

    // ---- main stream: s/t agg + packs (needs preproc + gemm_x3), then decoder ----
    cudaStreamWaitEvent(0, evPre, 0);
    k_agg_st<<<2048, 256>>>(bs, bt);
    k_decoder<<<dim3(64, 64), 256, DEC_SMEM>>>(adj);

    // ---- join ----
    cudaStreamWaitEvent(0, evB, 0);
}